// round 10
// baseline (speedup 1.0000x reference)
#include <cuda_runtime.h>
#include <math.h>
#include <stdint.h>

#define BATCH  4
#define SEQ    2048
#define DMODEL 768
#define NHEAD  12
#define HDIM   64
#define MTOT   (BATCH*SEQ)

// ---------------- scratch (static device globals; no allocs allowed) ----------------
__device__ float g_q[MTOT*DMODEL];     // Q/K/V stored with per-head dim permutation perm(d)=(d%8)*8+d/8
__device__ float g_k[MTOT*DMODEL];
__device__ float g_v[MTOT*DMODEL];
__device__ float g_att[MTOT*DMODEL];   // natural layout (consumed by O GEMM)
__device__ float g_xt[MTOT*DMODEL];    // x, tf32-rounded
__device__ float g_wq[DMODEL*DMODEL];  // weights, tf32-rounded
__device__ float g_wk[DMODEL*DMODEL];
__device__ float g_wv[DMODEL*DMODEL];
__device__ float g_wo[DMODEL*DMODEL];
__device__ unsigned char g_ctx[MTOT];
__device__ int g_is_byte;

// ---------------- is_context dtype detection ----------------
__global__ void detect_dtype_kernel(const unsigned char* __restrict__ p, int nbytes) {
    __shared__ int found;
    if (threadIdx.x == 0) found = 0;
    __syncthreads();
    int loc = 0;
    for (int i = threadIdx.x; i < nbytes; i += blockDim.x)
        if ((i & 3) == 1 && p[i] != 0) loc = 1;
    if (loc) atomicOr(&found, 1);
    __syncthreads();
    if (threadIdx.x == 0) g_is_byte = found;
}

__global__ void ctx_convert_kernel(const void* __restrict__ p, int n) {
    int i = blockIdx.x * blockDim.x + threadIdx.x;
    if (i >= n) return;
    int v;
    if (g_is_byte) v = ((const unsigned char*)p)[i];
    else           v = ((const int*)p)[i];
    g_ctx[i] = v ? 1 : 0;
}

// ---------------- tf32 / cp.async helpers ----------------
__device__ __forceinline__ uint32_t to_tf32(float x) {
    uint32_t r;
    asm("cvt.rna.tf32.f32 %0, %1;" : "=r"(r) : "f"(x));
    return r;
}

__device__ __forceinline__ void mma_tf32(float* d, const uint32_t* a, const uint32_t* b, const float* c) {
    asm volatile(
        "mma.sync.aligned.m16n8k8.row.col.f32.tf32.tf32.f32 "
        "{%0,%1,%2,%3}, {%4,%5,%6,%7}, {%8,%9}, {%10,%11,%12,%13};"
        : "=f"(d[0]), "=f"(d[1]), "=f"(d[2]), "=f"(d[3])
        : "r"(a[0]), "r"(a[1]), "r"(a[2]), "r"(a[3]),
          "r"(b[0]), "r"(b[1]),
          "f"(c[0]), "f"(c[1]), "f"(c[2]), "f"(c[3]));
}

__device__ __forceinline__ void cp_async16(uint32_t saddr, const void* gptr) {
    asm volatile("cp.async.cg.shared.global [%0], [%1], 16;" :: "r"(saddr), "l"(gptr));
}
__device__ __forceinline__ void cp_async4(uint32_t saddr, const void* gptr) {
    asm volatile("cp.async.ca.shared.global [%0], [%1], 4;" :: "r"(saddr), "l"(gptr));
}
__device__ __forceinline__ void cp_commit() {
    asm volatile("cp.async.commit_group;" ::: "memory");
}
__device__ __forceinline__ void cp_wait1() {
    asm volatile("cp.async.wait_group 1;" ::: "memory");
}
__device__ __forceinline__ void cp_wait0() {
    asm volatile("cp.async.wait_group 0;" ::: "memory");
}

// ---------------- tf32 pre-conversion ----------------
__global__ void tf32_convert_kernel(const float* __restrict__ src, float* __restrict__ dst, int n) {
    int i = blockIdx.x * blockDim.x + threadIdx.x;
    int stride = gridDim.x * blockDim.x;
    for (; i < n; i += stride)
        dst[i] = __uint_as_float(to_tf32(src[i]));
}

// ---------------- tf32 tensor-core GEMM, cp.async double-buffered ----------------
// cvt_out=1: outputs tf32-rounded AND written with per-head dim permutation
// (consumed by the attention mma with vectorized fragment loads).
#define GROW 36
#define GBUF (128*GROW)
__global__ __launch_bounds__(256, 2) void gemm_tc_kernel(
    const float* __restrict__ A,
    const float* __restrict__ W0, const float* __restrict__ b0, float* __restrict__ C0,
    const float* __restrict__ W1, const float* __restrict__ b1, float* __restrict__ C1,
    const float* __restrict__ W2, const float* __restrict__ b2, float* __restrict__ C2,
    int cvt_out)
{
    extern __shared__ float sm[];
    float* As = sm;               // [2][128][GROW]
    float* Bs = sm + 2 * GBUF;    // [2][128][GROW]

    int z = blockIdx.z;
    const float* W    = (z == 0) ? W0 : (z == 1) ? W1 : W2;
    const float* bias = (z == 0) ? b0 : (z == 1) ? b1 : b2;
    float*       C    = (z == 0) ? C0 : (z == 1) ? C1 : C2;

    int t    = threadIdx.x;
    int lane = t & 31;
    int warp = t >> 5;
    int g    = lane >> 2;
    int tq   = lane & 3;
    int wm   = (warp & 3) * 32;
    int wn   = (warp >> 2) * 64;
    int m0   = blockIdx.y * 128;
    int n0   = blockIdx.x * 128;

    float acc[2][8][4];
#pragma unroll
    for (int mt = 0; mt < 2; mt++)
#pragma unroll
        for (int nt = 0; nt < 8; nt++)
#pragma unroll
            for (int c = 0; c < 4; c++) acc[mt][nt][c] = 0.f;

    uint32_t as_s = (uint32_t)__cvta_generic_to_shared(As);
    uint32_t bs_s = (uint32_t)__cvta_generic_to_shared(Bs);

    auto stage = [&](int buf, int k0) {
        uint32_t bo = (uint32_t)buf * GBUF * 4;
#pragma unroll
        for (int u = 0; u < 4; u++) {
            int c = t + 256 * u;
            int row = c >> 3, c16 = c & 7;
            uint32_t soff = bo + (uint32_t)(row * GROW + c16 * 4) * 4;
            cp_async16(as_s + soff, &A[(size_t)(m0 + row) * DMODEL + k0 + c16 * 4]);
            cp_async16(bs_s + soff, &W[(size_t)(n0 + row) * DMODEL + k0 + c16 * 4]);
        }
        cp_commit();
    };

    stage(0, 0);

    const int NI = DMODEL / 32;   // 24
    for (int iter = 0; iter < NI; iter++) {
        int buf = iter & 1;
        if (iter + 1 < NI) {
            stage(buf ^ 1, (iter + 1) * 32);
            cp_wait1();
        } else {
            cp_wait0();
        }
        __syncthreads();

        const float* A2 = As + buf * GBUF;
        const float* B2 = Bs + buf * GBUF;

#pragma unroll
        for (int kk = 0; kk < 4; kk++) {
            int kb = kk * 8;
            uint32_t af[2][4];
#pragma unroll
            for (int mt = 0; mt < 2; mt++) {
                int rb = wm + mt * 16;
                af[mt][0] = __float_as_uint(A2[(rb + g    ) * GROW + kb + tq    ]);
                af[mt][1] = __float_as_uint(A2[(rb + g + 8) * GROW + kb + tq    ]);
                af[mt][2] = __float_as_uint(A2[(rb + g    ) * GROW + kb + tq + 4]);
                af[mt][3] = __float_as_uint(A2[(rb + g + 8) * GROW + kb + tq + 4]);
            }
#pragma unroll
            for (int nt = 0; nt < 8; nt++) {
                uint32_t bf[2];
                bf[0] = __float_as_uint(B2[(wn + nt*8 + g) * GROW + kb + tq    ]);
                bf[1] = __float_as_uint(B2[(wn + nt*8 + g) * GROW + kb + tq + 4]);
                mma_tf32(acc[0][nt], af[0], bf, acc[0][nt]);
                mma_tf32(acc[1][nt], af[1], bf, acc[1][nt]);
            }
        }
        __syncthreads();
    }

#pragma unroll
    for (int mt = 0; mt < 2; mt++) {
#pragma unroll
        for (int nt = 0; nt < 8; nt++) {
            int row = m0 + wm + mt * 16 + g;
            int col = n0 + wn + nt * 8 + 2 * tq;
            float b0v = bias[col], b1v = bias[col + 1];
            float v00 = acc[mt][nt][0] + b0v, v01 = acc[mt][nt][1] + b1v;
            float v10 = acc[mt][nt][2] + b0v, v11 = acc[mt][nt][3] + b1v;
            if (cvt_out) {
                // tf32-round + permuted write: d0 = nt*8+2tq -> perm = 16tq+nt (+8 for d0+1)
                v00 = __uint_as_float(to_tf32(v00)); v01 = __uint_as_float(to_tf32(v01));
                v10 = __uint_as_float(to_tf32(v10)); v11 = __uint_as_float(to_tf32(v11));
                int base = (col >> 6) << 6;               // head base
                int p0 = base + 16 * tq + nt;
                int p1 = p0 + 8;
                C[(size_t)row * DMODEL + p0]       = v00;
                C[(size_t)row * DMODEL + p1]       = v01;
                C[(size_t)(row + 8) * DMODEL + p0] = v10;
                C[(size_t)(row + 8) * DMODEL + p1] = v11;
            } else {
                *(float2*)&C[(size_t)row * DMODEL + col]       = make_float2(v00, v01);
                *(float2*)&C[(size_t)(row + 8) * DMODEL + col] = make_float2(v10, v11);
            }
        }
    }
}

// ---------------- Flash attention: permuted-layout vectorized fragments ----------------
// Q/K/V in gmem carry perm(d)=(d%8)*8+d/8 per head -> every mma fragment access
// becomes an LDS.128. P tile stored permuted too: width must be 60 (indices
// reach 16*3+3+8 = 59) -- round-9 used 36 and overflowed (the correctness bug).
#define PROW 60
__global__ __launch_bounds__(256, 2) void attn_tc_kernel() {
    __shared__ __align__(16) float Ksf[2][32][68];
    __shared__ __align__(16) float Vsf[2][32][68];
    __shared__ __align__(16) uint32_t Ps[8][16][PROW];
    __shared__ unsigned char cs[2][32];

    int t    = threadIdx.x;
    int lane = t & 31;
    int w    = t >> 5;
    int g    = lane >> 2;
    int tq   = lane & 3;

    int b  = blockIdx.z;
    int h  = blockIdx.y;
    int qrow = blockIdx.x * 128 + w * 16;

    // Q fragments from permuted gmem: logical dim ks*8+tqoff lives at tqoff*8+ks
    uint32_t qa[8][4];
    {
        const float* qb = &g_q[(size_t)(b * SEQ + qrow) * DMODEL + h * HDIM];
        float4 q0a = *(const float4*)&qb[(size_t)g       * DMODEL + tq*8];
        float4 q0b = *(const float4*)&qb[(size_t)g       * DMODEL + tq*8 + 4];
        float4 q1a = *(const float4*)&qb[(size_t)(g + 8) * DMODEL + tq*8];
        float4 q1b = *(const float4*)&qb[(size_t)(g + 8) * DMODEL + tq*8 + 4];
        float4 q2a = *(const float4*)&qb[(size_t)g       * DMODEL + (tq+4)*8];
        float4 q2b = *(const float4*)&qb[(size_t)g       * DMODEL + (tq+4)*8 + 4];
        float4 q3a = *(const float4*)&qb[(size_t)(g + 8) * DMODEL + (tq+4)*8];
        float4 q3b = *(const float4*)&qb[(size_t)(g + 8) * DMODEL + (tq+4)*8 + 4];
        float f0[8] = {q0a.x,q0a.y,q0a.z,q0a.w,q0b.x,q0b.y,q0b.z,q0b.w};
        float f1[8] = {q1a.x,q1a.y,q1a.z,q1a.w,q1b.x,q1b.y,q1b.z,q1b.w};
        float f2[8] = {q2a.x,q2a.y,q2a.z,q2a.w,q2b.x,q2b.y,q2b.z,q2b.w};
        float f3[8] = {q3a.x,q3a.y,q3a.z,q3a.w,q3b.x,q3b.y,q3b.z,q3b.w};
#pragma unroll
        for (int ks = 0; ks < 8; ks++) {
            qa[ks][0] = __float_as_uint(f0[ks] * 0.125f);
            qa[ks][1] = __float_as_uint(f1[ks] * 0.125f);
            qa[ks][2] = __float_as_uint(f2[ks] * 0.125f);
            qa[ks][3] = __float_as_uint(f3[ks] * 0.125f);
        }
    }
    float rf0 = g_ctx[b * SEQ + qrow + g    ] ? 1.f : 0.f;
    float rf1 = g_ctx[b * SEQ + qrow + g + 8] ? 1.f : 0.f;

    float o[8][4];
#pragma unroll
    for (int nt = 0; nt < 8; nt++)
#pragma unroll
        for (int c = 0; c < 4; c++) o[nt][c] = 0.f;
    float m0r = -1e30f, m1r = -1e30f, l0 = 0.f, l1 = 0.f;

    int key0 = t >> 4,         c40 = t & 15;
    int key1 = (t + 256) >> 4, c41 = (t + 256) & 15;
    size_t sbase = (size_t)(b * SEQ) * DMODEL + h * HDIM;

    uint32_t ks_s = (uint32_t)__cvta_generic_to_shared(&Ksf[0][0][0]);
    uint32_t vs_s = (uint32_t)__cvta_generic_to_shared(&Vsf[0][0][0]);
    uint32_t cs_s = (uint32_t)__cvta_generic_to_shared(&cs[0][0]);

    auto stage = [&](int buf, int kt) {
        size_t nb = sbase + (size_t)kt * DMODEL;
        uint32_t bo = (uint32_t)buf * (32 * 68 * 4);
        cp_async16(ks_s + bo + (key0 * 68 + c40 * 4) * 4, &g_k[nb + (size_t)key0 * DMODEL + c40 * 4]);
        cp_async16(ks_s + bo + (key1 * 68 + c41 * 4) * 4, &g_k[nb + (size_t)key1 * DMODEL + c41 * 4]);
        cp_async16(vs_s + bo + (key0 * 68 + c40 * 4) * 4, &g_v[nb + (size_t)key0 * DMODEL + c40 * 4]);
        cp_async16(vs_s + bo + (key1 * 68 + c41 * 4) * 4, &g_v[nb + (size_t)key1 * DMODEL + c41 * 4]);
        if (t < 8) cp_async4(cs_s + buf * 32 + t * 4, &g_ctx[b * SEQ + kt + t * 4]);
        cp_commit();
    };

    stage(0, 0);

    const int NT = SEQ / 32;   // 64 tiles
    for (int tile = 0; tile < NT; tile++) {
        int buf = tile & 1;
        if (tile + 1 < NT) {
            stage(buf ^ 1, (tile + 1) * 32);
            cp_wait1();
        } else {
            cp_wait0();
        }
        __syncthreads();

        const float (*Kt)[68] = Ksf[buf];
        const float (*Vt)[68] = Vsf[buf];

        // ---- S = Q K^T (16 x 32); K fragments via LDS.128 over permuted dims ----
        float sacc[4][4];
#pragma unroll
        for (int nt = 0; nt < 4; nt++)
#pragma unroll
            for (int c = 0; c < 4; c++) sacc[nt][c] = 0.f;
#pragma unroll
        for (int nt = 0; nt < 4; nt++) {
            const float* kr = &Kt[nt*8 + g][0];
            float4 b0a = *(const float4*)&kr[tq*8];
            float4 b0b = *(const float4*)&kr[tq*8 + 4];
            float4 b1a = *(const float4*)&kr[(tq+4)*8];
            float4 b1b = *(const float4*)&kr[(tq+4)*8 + 4];
            float e0[8] = {b0a.x,b0a.y,b0a.z,b0a.w,b0b.x,b0b.y,b0b.z,b0b.w};
            float e1[8] = {b1a.x,b1a.y,b1a.z,b1a.w,b1b.x,b1b.y,b1b.z,b1b.w};
#pragma unroll
            for (int ks = 0; ks < 8; ks++) {
                uint32_t bf[2];
                bf[0] = __float_as_uint(e0[ks]);
                bf[1] = __float_as_uint(e1[ks]);
                mma_tf32(sacc[nt], qa[ks], bf, sacc[nt]);
            }
        }

        // ---- mask (additive -1e30, branchless; == reference) ----
#pragma unroll
        for (int nt = 0; nt < 4; nt++) {
            int col = nt*8 + 2*tq;
            float k0m = cs[buf][col    ] ? 0.f : -1e30f;
            float k1m = cs[buf][col + 1] ? 0.f : -1e30f;
            sacc[nt][0] = fmaf(rf0, k0m, sacc[nt][0]);
            sacc[nt][1] = fmaf(rf0, k1m, sacc[nt][1]);
            sacc[nt][2] = fmaf(rf1, k0m, sacc[nt][2]);
            sacc[nt][3] = fmaf(rf1, k1m, sacc[nt][3]);
        }

        // ---- online softmax (MUFU exps) ----
        float mx0 = -1e30f, mx1 = -1e30f;
#pragma unroll
        for (int nt = 0; nt < 4; nt++) {
            mx0 = fmaxf(mx0, fmaxf(sacc[nt][0], sacc[nt][1]));
            mx1 = fmaxf(mx1, fmaxf(sacc[nt][2], sacc[nt][3]));
        }
        mx0 = fmaxf(mx0, __shfl_xor_sync(0xffffffffu, mx0, 1));
        mx0 = fmaxf(mx0, __shfl_xor_sync(0xffffffffu, mx0, 2));
        mx1 = fmaxf(mx1, __shfl_xor_sync(0xffffffffu, mx1, 1));
        mx1 = fmaxf(mx1, __shfl_xor_sync(0xffffffffu, mx1, 2));

        float mn0 = fmaxf(m0r, mx0), mn1 = fmaxf(m1r, mx1);
        float corr0 = __expf(m0r - mn0), corr1 = __expf(m1r - mn1);
        m0r = mn0; m1r = mn1;

        float rs0 = 0.f, rs1 = 0.f;
        __syncwarp();
        // P stored PERMUTED: element (row, col) at [row][perm(col)]; col=nt*8+2tq -> 16tq+nt
#pragma unroll
        for (int nt = 0; nt < 4; nt++) {
            float p00 = __expf(sacc[nt][0] - mn0);
            float p01 = __expf(sacc[nt][1] - mn0);
            float p10 = __expf(sacc[nt][2] - mn1);
            float p11 = __expf(sacc[nt][3] - mn1);
            rs0 += p00 + p01; rs1 += p10 + p11;
            int pc = 16*tq + nt;
            Ps[w][g    ][pc    ] = to_tf32(p00);
            Ps[w][g    ][pc + 8] = to_tf32(p01);
            Ps[w][g + 8][pc    ] = to_tf32(p10);
            Ps[w][g + 8][pc + 8] = to_tf32(p11);
        }
        rs0 += __shfl_xor_sync(0xffffffffu, rs0, 1);
        rs0 += __shfl_xor_sync(0xffffffffu, rs0, 2);
        rs1 += __shfl_xor_sync(0xffffffffu, rs1, 1);
        rs1 += __shfl_xor_sync(0xffffffffu, rs1, 2);
        l0 = l0 * corr0 + rs0;
        l1 = l1 * corr1 + rs1;

#pragma unroll
        for (int nt = 0; nt < 8; nt++) {
            o[nt][0] *= corr0; o[nt][1] *= corr0;
            o[nt][2] *= corr1; o[nt][3] *= corr1;
        }
        __syncwarp();

        // ---- O += P V: P frags via 4 LDS.128, V frags via LDS.128 over permuted dims ----
        uint4 a00 = *(const uint4*)&Ps[w][g    ][tq*8];        // logical P[g][ks*8+tq], ks=0..3
        uint4 a01 = *(const uint4*)&Ps[w][g + 8][tq*8];
        uint4 a10 = *(const uint4*)&Ps[w][g    ][(tq+4)*8];    // logical P[g][ks*8+tq+4]
        uint4 a11 = *(const uint4*)&Ps[w][g + 8][(tq+4)*8];
        uint32_t pa0[4] = {a00.x, a00.y, a00.z, a00.w};
        uint32_t pa1[4] = {a01.x, a01.y, a01.z, a01.w};
        uint32_t pa2[4] = {a10.x, a10.y, a10.z, a10.w};
        uint32_t pa3[4] = {a11.x, a11.y, a11.z, a11.w};
#pragma unroll
        for (int ks = 0; ks < 4; ks++) {
            uint32_t ap[4] = {pa0[ks], pa1[ks], pa2[ks], pa3[ks]};
            const float* vr0 = &Vt[ks*8 + tq    ][0];
            const float* vr1 = &Vt[ks*8 + tq + 4][0];
            float4 v0a = *(const float4*)&vr0[g*8];
            float4 v0b = *(const float4*)&vr0[g*8 + 4];
            float4 v1a = *(const float4*)&vr1[g*8];
            float4 v1b = *(const float4*)&vr1[g*8 + 4];
            float w0[8] = {v0a.x,v0a.y,v0a.z,v0a.w,v0b.x,v0b.y,v0b.z,v0b.w};
            float w1[8] = {v1a.x,v1a.y,v1a.z,v1a.w,v1b.x,v1b.y,v1b.z,v1b.w};
#pragma unroll
            for (int nt = 0; nt < 8; nt++) {
                uint32_t bf[2];
                bf[0] = __float_as_uint(w0[nt]);
                bf[1] = __float_as_uint(w1[nt]);
                mma_tf32(o[nt], ap, bf, o[nt]);
            }
        }
        __syncthreads();
    }

    // ---- normalize + write (NATURAL layout; consumed by O GEMM) ----
    float inv0 = 1.f / l0, inv1 = 1.f / l1;
    float* ob = &g_att[(size_t)(b * SEQ + qrow) * DMODEL + h * HDIM];
#pragma unroll
    for (int nt = 0; nt < 8; nt++) {
        int col = nt*8 + 2*tq;
        float2 o0 = make_float2(__uint_as_float(to_tf32(o[nt][0] * inv0)),
                                __uint_as_float(to_tf32(o[nt][1] * inv0)));
        float2 o1 = make_float2(__uint_as_float(to_tf32(o[nt][2] * inv1)),
                                __uint_as_float(to_tf32(o[nt][3] * inv1)));
        *(float2*)&ob[(size_t)g       * DMODEL + col] = o0;
        *(float2*)&ob[(size_t)(g + 8) * DMODEL + col] = o1;
    }
}

// ---------------- launch ----------------
extern "C" void kernel_launch(void* const* d_in, const int* in_sizes, int n_in,
                              void* d_out, int out_size) {
    const float* x   = (const float*)d_in[0];
    const void*  ctx = d_in[1];
    const float* Wq  = (const float*)d_in[2];
    const float* bq  = (const float*)d_in[3];
    const float* Wk  = (const float*)d_in[4];
    const float* bk  = (const float*)d_in[5];
    const float* Wv  = (const float*)d_in[6];
    const float* bv  = (const float*)d_in[7];
    const float* Wo  = (const float*)d_in[8];
    const float* bo  = (const float*)d_in[9];
    float* out = (float*)d_out;

    float *qb, *kb, *vb, *ab, *xt, *wq, *wk, *wv, *wo;
    cudaGetSymbolAddress((void**)&qb, g_q);
    cudaGetSymbolAddress((void**)&kb, g_k);
    cudaGetSymbolAddress((void**)&vb, g_v);
    cudaGetSymbolAddress((void**)&ab, g_att);
    cudaGetSymbolAddress((void**)&xt, g_xt);
    cudaGetSymbolAddress((void**)&wq, g_wq);
    cudaGetSymbolAddress((void**)&wk, g_wk);
    cudaGetSymbolAddress((void**)&wv, g_wv);
    cudaGetSymbolAddress((void**)&wo, g_wo);

    static bool attr_set = false;
    if (!attr_set) {
        cudaFuncSetAttribute(gemm_tc_kernel, cudaFuncAttributeMaxDynamicSharedMemorySize,
                             4 * GBUF * (int)sizeof(float));
        attr_set = true;
    }

    detect_dtype_kernel<<<1, 1024>>>((const unsigned char*)ctx, MTOT);
    ctx_convert_kernel<<<(MTOT + 255) / 256, 256>>>(ctx, MTOT);

    tf32_convert_kernel<<<592, 256>>>(x,  xt, MTOT * DMODEL);
    tf32_convert_kernel<<<592, 256>>>(Wq, wq, DMODEL * DMODEL);
    tf32_convert_kernel<<<592, 256>>>(Wk, wk, DMODEL * DMODEL);
    tf32_convert_kernel<<<592, 256>>>(Wv, wv, DMODEL * DMODEL);
    tf32_convert_kernel<<<592, 256>>>(Wo, wo, DMODEL * DMODEL);

    int smem = 4 * GBUF * (int)sizeof(float);   // 73728 B

    dim3 gqkv(DMODEL / 128, MTOT / 128, 3);
    gemm_tc_kernel<<<gqkv, 256, smem>>>(xt, wq, bq, qb, wk, bk, kb, wv, bv, vb, 1);

    attn_tc_kernel<<<dim3(SEQ / 128, NHEAD, BATCH), 256>>>();

    dim3 go(DMODEL / 128, MTOT / 128, 1);
    gemm_tc_kernel<<<go, 256, smem>>>(ab, wo, bo, out, wo, bo, out, wo, bo, out, 0);
}

// round 11
// speedup vs baseline: 1.0625x; 1.0625x over previous
#include <cuda_runtime.h>
#include <math.h>
#include <stdint.h>

#define BATCH  4
#define SEQ    2048
#define DMODEL 768
#define NHEAD  12
#define HDIM   64
#define MTOT   (BATCH*SEQ)

// ---------------- scratch (static device globals; no allocs allowed) ----------------
__device__ float g_q[MTOT*DMODEL];
__device__ float g_k[MTOT*DMODEL];
__device__ float g_v[MTOT*DMODEL];
__device__ float g_att[MTOT*DMODEL];
__device__ float g_xt[MTOT*DMODEL];        // x, tf32-rounded
__device__ float g_wq[DMODEL*DMODEL];      // weights, tf32-rounded
__device__ float g_wk[DMODEL*DMODEL];
__device__ float g_wv[DMODEL*DMODEL];
__device__ float g_wo[DMODEL*DMODEL];
__device__ unsigned char g_ctx[MTOT];
__device__ int g_is_byte;

// ---------------- is_context dtype detection ----------------
__global__ void detect_dtype_kernel(const unsigned char* __restrict__ p, int nbytes) {
    __shared__ int found;
    if (threadIdx.x == 0) found = 0;
    __syncthreads();
    int loc = 0;
    for (int i = threadIdx.x; i < nbytes; i += blockDim.x)
        if ((i & 3) == 1 && p[i] != 0) loc = 1;
    if (loc) atomicOr(&found, 1);
    __syncthreads();
    if (threadIdx.x == 0) g_is_byte = found;
}

__global__ void ctx_convert_kernel(const void* __restrict__ p, int n) {
    int i = blockIdx.x * blockDim.x + threadIdx.x;
    if (i >= n) return;
    int v;
    if (g_is_byte) v = ((const unsigned char*)p)[i];
    else           v = ((const int*)p)[i];
    g_ctx[i] = v ? 1 : 0;
}

// ---------------- tf32 / cp.async helpers ----------------
__device__ __forceinline__ uint32_t to_tf32(float x) {
    uint32_t r;
    asm("cvt.rna.tf32.f32 %0, %1;" : "=r"(r) : "f"(x));
    return r;
}

__device__ __forceinline__ void mma_tf32(float* d, const uint32_t* a, const uint32_t* b, const float* c) {
    asm volatile(
        "mma.sync.aligned.m16n8k8.row.col.f32.tf32.tf32.f32 "
        "{%0,%1,%2,%3}, {%4,%5,%6,%7}, {%8,%9}, {%10,%11,%12,%13};"
        : "=f"(d[0]), "=f"(d[1]), "=f"(d[2]), "=f"(d[3])
        : "r"(a[0]), "r"(a[1]), "r"(a[2]), "r"(a[3]),
          "r"(b[0]), "r"(b[1]),
          "f"(c[0]), "f"(c[1]), "f"(c[2]), "f"(c[3]));
}

__device__ __forceinline__ void cp_async16(uint32_t saddr, const void* gptr) {
    asm volatile("cp.async.cg.shared.global [%0], [%1], 16;" :: "r"(saddr), "l"(gptr));
}
__device__ __forceinline__ void cp_async4(uint32_t saddr, const void* gptr) {
    asm volatile("cp.async.ca.shared.global [%0], [%1], 4;" :: "r"(saddr), "l"(gptr));
}
__device__ __forceinline__ void cp_commit() {
    asm volatile("cp.async.commit_group;" ::: "memory");
}
__device__ __forceinline__ void cp_wait1() {
    asm volatile("cp.async.wait_group 1;" ::: "memory");
}
__device__ __forceinline__ void cp_wait0() {
    asm volatile("cp.async.wait_group 0;" ::: "memory");
}

// ---------------- fused tf32 pre-conversion: x + all 4 weight matrices in ONE launch ----------------
#define NX (MTOT*DMODEL)          // 6291456
#define NW (DMODEL*DMODEL)        // 589824
__global__ void tf32_convert_all_kernel(const float* __restrict__ x,
                                        const float* __restrict__ Wq,
                                        const float* __restrict__ Wk,
                                        const float* __restrict__ Wv,
                                        const float* __restrict__ Wo) {
    int total = NX + 4 * NW;
    int stride = gridDim.x * blockDim.x;
    for (int i = blockIdx.x * blockDim.x + threadIdx.x; i < total; i += stride) {
        if (i < NX) {
            g_xt[i] = __uint_as_float(to_tf32(x[i]));
        } else {
            int j = i - NX;
            int wsel = j / NW;
            int off  = j - wsel * NW;
            const float* src = (wsel == 0) ? Wq : (wsel == 1) ? Wk : (wsel == 2) ? Wv : Wo;
            float*       dst = (wsel == 0) ? g_wq : (wsel == 1) ? g_wk : (wsel == 2) ? g_wv : g_wo;
            dst[off] = __uint_as_float(to_tf32(src[off]));
        }
    }
}

// ---------------- tf32 tensor-core GEMM, cp.async double-buffered (round-8, kept) ----------------
#define GROW 36
#define GBUF (128*GROW)
__global__ __launch_bounds__(256, 2) void gemm_tc_kernel(
    const float* __restrict__ A,
    const float* __restrict__ W0, const float* __restrict__ b0, float* __restrict__ C0,
    const float* __restrict__ W1, const float* __restrict__ b1, float* __restrict__ C1,
    const float* __restrict__ W2, const float* __restrict__ b2, float* __restrict__ C2,
    int cvt_out)
{
    extern __shared__ float sm[];
    float* As = sm;               // [2][128][GROW]
    float* Bs = sm + 2 * GBUF;    // [2][128][GROW]

    int z = blockIdx.z;
    const float* W    = (z == 0) ? W0 : (z == 1) ? W1 : W2;
    const float* bias = (z == 0) ? b0 : (z == 1) ? b1 : b2;
    float*       C    = (z == 0) ? C0 : (z == 1) ? C1 : C2;

    int t    = threadIdx.x;
    int lane = t & 31;
    int warp = t >> 5;
    int g    = lane >> 2;
    int tq   = lane & 3;
    int wm   = (warp & 3) * 32;
    int wn   = (warp >> 2) * 64;
    int m0   = blockIdx.y * 128;
    int n0   = blockIdx.x * 128;

    float acc[2][8][4];
#pragma unroll
    for (int mt = 0; mt < 2; mt++)
#pragma unroll
        for (int nt = 0; nt < 8; nt++)
#pragma unroll
            for (int c = 0; c < 4; c++) acc[mt][nt][c] = 0.f;

    uint32_t as_s = (uint32_t)__cvta_generic_to_shared(As);
    uint32_t bs_s = (uint32_t)__cvta_generic_to_shared(Bs);

    auto stage = [&](int buf, int k0) {
        uint32_t bo = (uint32_t)buf * GBUF * 4;
#pragma unroll
        for (int u = 0; u < 4; u++) {
            int c = t + 256 * u;
            int row = c >> 3, c16 = c & 7;
            uint32_t soff = bo + (uint32_t)(row * GROW + c16 * 4) * 4;
            cp_async16(as_s + soff, &A[(size_t)(m0 + row) * DMODEL + k0 + c16 * 4]);
            cp_async16(bs_s + soff, &W[(size_t)(n0 + row) * DMODEL + k0 + c16 * 4]);
        }
        cp_commit();
    };

    stage(0, 0);

    const int NI = DMODEL / 32;   // 24
    for (int iter = 0; iter < NI; iter++) {
        int buf = iter & 1;
        if (iter + 1 < NI) {
            stage(buf ^ 1, (iter + 1) * 32);
            cp_wait1();
        } else {
            cp_wait0();
        }
        __syncthreads();

        const float* A2 = As + buf * GBUF;
        const float* B2 = Bs + buf * GBUF;

#pragma unroll
        for (int kk = 0; kk < 4; kk++) {
            int kb = kk * 8;
            uint32_t af[2][4];
#pragma unroll
            for (int mt = 0; mt < 2; mt++) {
                int rb = wm + mt * 16;
                af[mt][0] = __float_as_uint(A2[(rb + g    ) * GROW + kb + tq    ]);
                af[mt][1] = __float_as_uint(A2[(rb + g + 8) * GROW + kb + tq    ]);
                af[mt][2] = __float_as_uint(A2[(rb + g    ) * GROW + kb + tq + 4]);
                af[mt][3] = __float_as_uint(A2[(rb + g + 8) * GROW + kb + tq + 4]);
            }
#pragma unroll
            for (int nt = 0; nt < 8; nt++) {
                uint32_t bf[2];
                bf[0] = __float_as_uint(B2[(wn + nt*8 + g) * GROW + kb + tq    ]);
                bf[1] = __float_as_uint(B2[(wn + nt*8 + g) * GROW + kb + tq + 4]);
                mma_tf32(acc[0][nt], af[0], bf, acc[0][nt]);
                mma_tf32(acc[1][nt], af[1], bf, acc[1][nt]);
            }
        }
        __syncthreads();
    }

#pragma unroll
    for (int mt = 0; mt < 2; mt++) {
#pragma unroll
        for (int nt = 0; nt < 8; nt++) {
            int row = m0 + wm + mt * 16 + g;
            int col = n0 + wn + nt * 8 + 2 * tq;
            float b0v = bias[col], b1v = bias[col + 1];
            float v00 = acc[mt][nt][0] + b0v, v01 = acc[mt][nt][1] + b1v;
            float v10 = acc[mt][nt][2] + b0v, v11 = acc[mt][nt][3] + b1v;
            if (cvt_out) {
                v00 = __uint_as_float(to_tf32(v00)); v01 = __uint_as_float(to_tf32(v01));
                v10 = __uint_as_float(to_tf32(v10)); v11 = __uint_as_float(to_tf32(v11));
            }
            *(float2*)&C[(size_t)row * DMODEL + col]       = make_float2(v00, v01);
            *(float2*)&C[(size_t)(row + 8) * DMODEL + col] = make_float2(v10, v11);
        }
    }
}

// ---------------- Flash attention: cp.async double-buffered, 2 CTAs/SM (round-8, kept) ----------------
__global__ __launch_bounds__(256, 2) void attn_tc_kernel() {
    __shared__ __align__(16) float Ksf[2][32][68];
    __shared__ __align__(16) float Vsf[2][32][68];
    __shared__ uint32_t Ps[8][16][36];
    __shared__ unsigned char cs[2][32];

    int t    = threadIdx.x;
    int lane = t & 31;
    int w    = t >> 5;
    int g    = lane >> 2;
    int tq   = lane & 3;

    int b  = blockIdx.z;
    int h  = blockIdx.y;
    int qrow = blockIdx.x * 128 + w * 16;

    // Q fragments: already tf32-rounded; *0.125f (2^-3) is exact on tf32
    uint32_t qa[8][4];
    {
        const float* qb = &g_q[(size_t)(b * SEQ + qrow) * DMODEL + h * HDIM];
#pragma unroll
        for (int ks = 0; ks < 8; ks++) {
            qa[ks][0] = __float_as_uint(qb[(size_t)g       * DMODEL + ks*8 + tq    ] * 0.125f);
            qa[ks][1] = __float_as_uint(qb[(size_t)(g + 8) * DMODEL + ks*8 + tq    ] * 0.125f);
            qa[ks][2] = __float_as_uint(qb[(size_t)g       * DMODEL + ks*8 + tq + 4] * 0.125f);
            qa[ks][3] = __float_as_uint(qb[(size_t)(g + 8) * DMODEL + ks*8 + tq + 4] * 0.125f);
        }
    }
    float rf0 = g_ctx[b * SEQ + qrow + g    ] ? 1.f : 0.f;
    float rf1 = g_ctx[b * SEQ + qrow + g + 8] ? 1.f : 0.f;

    float o[8][4];
#pragma unroll
    for (int nt = 0; nt < 8; nt++)
#pragma unroll
        for (int c = 0; c < 4; c++) o[nt][c] = 0.f;
    float m0r = -1e30f, m1r = -1e30f, l0 = 0.f, l1 = 0.f;

    int key0 = t >> 4,         c40 = t & 15;
    int key1 = (t + 256) >> 4, c41 = (t + 256) & 15;
    size_t sbase = (size_t)(b * SEQ) * DMODEL + h * HDIM;

    uint32_t ks_s = (uint32_t)__cvta_generic_to_shared(&Ksf[0][0][0]);
    uint32_t vs_s = (uint32_t)__cvta_generic_to_shared(&Vsf[0][0][0]);
    uint32_t cs_s = (uint32_t)__cvta_generic_to_shared(&cs[0][0]);

    auto stage = [&](int buf, int kt) {
        size_t nb = sbase + (size_t)kt * DMODEL;
        uint32_t bo = (uint32_t)buf * (32 * 68 * 4);
        cp_async16(ks_s + bo + (key0 * 68 + c40 * 4) * 4, &g_k[nb + (size_t)key0 * DMODEL + c40 * 4]);
        cp_async16(ks_s + bo + (key1 * 68 + c41 * 4) * 4, &g_k[nb + (size_t)key1 * DMODEL + c41 * 4]);
        cp_async16(vs_s + bo + (key0 * 68 + c40 * 4) * 4, &g_v[nb + (size_t)key0 * DMODEL + c40 * 4]);
        cp_async16(vs_s + bo + (key1 * 68 + c41 * 4) * 4, &g_v[nb + (size_t)key1 * DMODEL + c41 * 4]);
        if (t < 8) cp_async4(cs_s + buf * 32 + t * 4, &g_ctx[b * SEQ + kt + t * 4]);
        cp_commit();
    };

    stage(0, 0);

    const int NT = SEQ / 32;   // 64 tiles
    for (int tile = 0; tile < NT; tile++) {
        int buf = tile & 1;
        if (tile + 1 < NT) {
            stage(buf ^ 1, (tile + 1) * 32);
            cp_wait1();
        } else {
            cp_wait0();
        }
        __syncthreads();

        const float (*Kt)[68] = Ksf[buf];
        const float (*Vt)[68] = Vsf[buf];

        // ---- S = Q K^T (16 x 32) ----
        float sacc[4][4];
#pragma unroll
        for (int nt = 0; nt < 4; nt++)
#pragma unroll
            for (int c = 0; c < 4; c++) sacc[nt][c] = 0.f;
#pragma unroll
        for (int ks = 0; ks < 8; ks++) {
#pragma unroll
            for (int nt = 0; nt < 4; nt++) {
                uint32_t bf[2];
                bf[0] = __float_as_uint(Kt[nt*8 + g][ks*8 + tq    ]);
                bf[1] = __float_as_uint(Kt[nt*8 + g][ks*8 + tq + 4]);
                mma_tf32(sacc[nt], qa[ks], bf, sacc[nt]);
            }
        }

        // ---- mask (additive -1e30, branchless; == reference) ----
#pragma unroll
        for (int nt = 0; nt < 4; nt++) {
            int col = nt*8 + 2*tq;
            float k0m = cs[buf][col    ] ? 0.f : -1e30f;
            float k1m = cs[buf][col + 1] ? 0.f : -1e30f;
            sacc[nt][0] = fmaf(rf0, k0m, sacc[nt][0]);
            sacc[nt][1] = fmaf(rf0, k1m, sacc[nt][1]);
            sacc[nt][2] = fmaf(rf1, k0m, sacc[nt][2]);
            sacc[nt][3] = fmaf(rf1, k1m, sacc[nt][3]);
        }

        // ---- online softmax (MUFU exps) ----
        float mx0 = -1e30f, mx1 = -1e30f;
#pragma unroll
        for (int nt = 0; nt < 4; nt++) {
            mx0 = fmaxf(mx0, fmaxf(sacc[nt][0], sacc[nt][1]));
            mx1 = fmaxf(mx1, fmaxf(sacc[nt][2], sacc[nt][3]));
        }
        mx0 = fmaxf(mx0, __shfl_xor_sync(0xffffffffu, mx0, 1));
        mx0 = fmaxf(mx0, __shfl_xor_sync(0xffffffffu, mx0, 2));
        mx1 = fmaxf(mx1, __shfl_xor_sync(0xffffffffu, mx1, 1));
        mx1 = fmaxf(mx1, __shfl_xor_sync(0xffffffffu, mx1, 2));

        float mn0 = fmaxf(m0r, mx0), mn1 = fmaxf(m1r, mx1);
        float corr0 = __expf(m0r - mn0), corr1 = __expf(m1r - mn1);
        m0r = mn0; m1r = mn1;

        float rs0 = 0.f, rs1 = 0.f;
        __syncwarp();
#pragma unroll
        for (int nt = 0; nt < 4; nt++) {
            int col = nt*8 + 2*tq;
            float p00 = __expf(sacc[nt][0] - mn0);
            float p01 = __expf(sacc[nt][1] - mn0);
            float p10 = __expf(sacc[nt][2] - mn1);
            float p11 = __expf(sacc[nt][3] - mn1);
            rs0 += p00 + p01; rs1 += p10 + p11;
            Ps[w][g    ][col    ] = to_tf32(p00);
            Ps[w][g    ][col + 1] = to_tf32(p01);
            Ps[w][g + 8][col    ] = to_tf32(p10);
            Ps[w][g + 8][col + 1] = to_tf32(p11);
        }
        rs0 += __shfl_xor_sync(0xffffffffu, rs0, 1);
        rs0 += __shfl_xor_sync(0xffffffffu, rs0, 2);
        rs1 += __shfl_xor_sync(0xffffffffu, rs1, 1);
        rs1 += __shfl_xor_sync(0xffffffffu, rs1, 2);
        l0 = l0 * corr0 + rs0;
        l1 = l1 * corr1 + rs1;

#pragma unroll
        for (int nt = 0; nt < 8; nt++) {
            o[nt][0] *= corr0; o[nt][1] *= corr0;
            o[nt][2] *= corr1; o[nt][3] *= corr1;
        }
        __syncwarp();

        // ---- O += P V  (16 x 64, k=32) ----
#pragma unroll
        for (int ks = 0; ks < 4; ks++) {
            uint32_t ap[4];
            ap[0] = Ps[w][g    ][ks*8 + tq    ];
            ap[1] = Ps[w][g + 8][ks*8 + tq    ];
            ap[2] = Ps[w][g    ][ks*8 + tq + 4];
            ap[3] = Ps[w][g + 8][ks*8 + tq + 4];
#pragma unroll
            for (int nt = 0; nt < 8; nt++) {
                uint32_t bf[2];
                bf[0] = __float_as_uint(Vt[ks*8 + tq    ][nt*8 + g]);
                bf[1] = __float_as_uint(Vt[ks*8 + tq + 4][nt*8 + g]);
                mma_tf32(o[nt], ap, bf, o[nt]);
            }
        }
        __syncthreads();
    }

    // ---- normalize + write (tf32-rounded: consumed by the O GEMM's raw path) ----
    float inv0 = 1.f / l0, inv1 = 1.f / l1;
    float* ob = &g_att[(size_t)(b * SEQ + qrow) * DMODEL + h * HDIM];
#pragma unroll
    for (int nt = 0; nt < 8; nt++) {
        int col = nt*8 + 2*tq;
        float2 o0 = make_float2(__uint_as_float(to_tf32(o[nt][0] * inv0)),
                                __uint_as_float(to_tf32(o[nt][1] * inv0)));
        float2 o1 = make_float2(__uint_as_float(to_tf32(o[nt][2] * inv1)),
                                __uint_as_float(to_tf32(o[nt][3] * inv1)));
        *(float2*)&ob[(size_t)g       * DMODEL + col] = o0;
        *(float2*)&ob[(size_t)(g + 8) * DMODEL + col] = o1;
    }
}

// ---------------- launch ----------------
extern "C" void kernel_launch(void* const* d_in, const int* in_sizes, int n_in,
                              void* d_out, int out_size) {
    const float* x   = (const float*)d_in[0];
    const void*  ctx = d_in[1];
    const float* Wq  = (const float*)d_in[2];
    const float* bq  = (const float*)d_in[3];
    const float* Wk  = (const float*)d_in[4];
    const float* bk  = (const float*)d_in[5];
    const float* Wv  = (const float*)d_in[6];
    const float* bv  = (const float*)d_in[7];
    const float* Wo  = (const float*)d_in[8];
    const float* bo  = (const float*)d_in[9];
    float* out = (float*)d_out;

    float *qb, *kb, *vb, *ab, *xt, *wq, *wk, *wv, *wo;
    cudaGetSymbolAddress((void**)&qb, g_q);
    cudaGetSymbolAddress((void**)&kb, g_k);
    cudaGetSymbolAddress((void**)&vb, g_v);
    cudaGetSymbolAddress((void**)&ab, g_att);
    cudaGetSymbolAddress((void**)&xt, g_xt);
    cudaGetSymbolAddress((void**)&wq, g_wq);
    cudaGetSymbolAddress((void**)&wk, g_wk);
    cudaGetSymbolAddress((void**)&wv, g_wv);
    cudaGetSymbolAddress((void**)&wo, g_wo);
    (void)xt; (void)wq; (void)wk; (void)wv; (void)wo;

    static bool attr_set = false;
    if (!attr_set) {
        cudaFuncSetAttribute(gemm_tc_kernel, cudaFuncAttributeMaxDynamicSharedMemorySize,
                             4 * GBUF * (int)sizeof(float));
        attr_set = true;
    }

    detect_dtype_kernel<<<1, 1024>>>((const unsigned char*)ctx, MTOT);
    ctx_convert_kernel<<<(MTOT + 255) / 256, 256>>>(ctx, MTOT);

    // single fused tf32 pre-conversion (x + 4 weights)
    tf32_convert_all_kernel<<<1184, 256>>>(x, Wq, Wk, Wv, Wo);

    int smem = 4 * GBUF * (int)sizeof(float);   // 73728 B

    dim3 gqkv(DMODEL / 128, MTOT / 128, 3);
    gemm_tc_kernel<<<gqkv, 256, smem>>>(xt, wq, bq, qb, wk, bk, kb, wv, bv, vb, 1);

    attn_tc_kernel<<<dim3(SEQ / 128, NHEAD, BATCH), 256>>>();

    dim3 go(DMODEL / 128, MTOT / 128, 1);
    gemm_tc_kernel<<<go, 256, smem>>>(ab, wo, bo, out, wo, bo, out, wo, bo, out, 0);
}

// round 12
// speedup vs baseline: 1.2658x; 1.1914x over previous
#include <cuda_runtime.h>
#include <math.h>
#include <stdint.h>

#define BATCH  4
#define SEQ    2048
#define DMODEL 768
#define NHEAD  12
#define HDIM   64
#define MTOT   (BATCH*SEQ)

// ---------------- scratch (static device globals; no allocs allowed) ----------------
__device__ float g_q[MTOT*DMODEL];     // Q/K/V in ctx-sorted ROW order (per batch)
__device__ float g_k[MTOT*DMODEL];
__device__ float g_v[MTOT*DMODEL];
__device__ float g_att[MTOT*DMODEL];   // ORIGINAL row order (consumed by O GEMM)
__device__ float g_xt[MTOT*DMODEL];    // x, tf32-rounded
__device__ float g_wq[DMODEL*DMODEL];  // weights, tf32-rounded
__device__ float g_wk[DMODEL*DMODEL];
__device__ float g_wv[DMODEL*DMODEL];
__device__ float g_wo[DMODEL*DMODEL];
__device__ unsigned char g_ctx[MTOT];
__device__ int g_perm[MTOT];           // perm[new] = old  (per batch, ctx rows first)
__device__ int g_inv[MTOT];            // inv[old] = new
__device__ int g_nctx[BATCH];
__device__ int g_is_byte;

// ---------------- is_context dtype detection ----------------
__global__ void detect_dtype_kernel(const unsigned char* __restrict__ p, int nbytes) {
    __shared__ int found;
    if (threadIdx.x == 0) found = 0;
    __syncthreads();
    int loc = 0;
    for (int i = threadIdx.x; i < nbytes; i += blockDim.x)
        if ((i & 3) == 1 && p[i] != 0) loc = 1;
    if (loc) atomicOr(&found, 1);
    __syncthreads();
    if (threadIdx.x == 0) g_is_byte = found;
}

__global__ void ctx_convert_kernel(const void* __restrict__ p, int n) {
    int i = blockIdx.x * blockDim.x + threadIdx.x;
    if (i >= n) return;
    int v;
    if (g_is_byte) v = ((const unsigned char*)p)[i];
    else           v = ((const int*)p)[i];
    g_ctx[i] = v ? 1 : 0;
}

// ---------------- stable partition (ctx first) per batch: block scan ----------------
// grid = BATCH, block = 256; 8 elements/thread.
__global__ void build_perm_kernel() {
    __shared__ int partial[256];
    int b = blockIdx.x, t = threadIdx.x;
    int flags[8];
    int cnt = 0;
#pragma unroll
    for (int i = 0; i < 8; i++) {
        flags[i] = g_ctx[b * SEQ + t * 8 + i];
        cnt += flags[i];
    }
    partial[t] = cnt;
    __syncthreads();
    // Hillis-Steele inclusive scan
    for (int off = 1; off < 256; off <<= 1) {
        int v = (t >= off) ? partial[t - off] : 0;
        __syncthreads();
        partial[t] += v;
        __syncthreads();
    }
    int total = partial[255];
    int run = partial[t] - cnt;   // #ctx before this thread's chunk
#pragma unroll
    for (int i = 0; i < 8; i++) {
        int old = t * 8 + i;
        int newpos;
        if (flags[i]) { newpos = run; run++; }
        else          { newpos = total + (old - run); }   // old - (#ctx before old)
        g_perm[b * SEQ + newpos] = old;
        g_inv[b * SEQ + old] = newpos;
    }
    if (t == 0) g_nctx[b] = total;
}

// ---------------- tf32 / cp.async helpers ----------------
__device__ __forceinline__ uint32_t to_tf32(float x) {
    uint32_t r;
    asm("cvt.rna.tf32.f32 %0, %1;" : "=r"(r) : "f"(x));
    return r;
}

__device__ __forceinline__ void mma_tf32(float* d, const uint32_t* a, const uint32_t* b, const float* c) {
    asm volatile(
        "mma.sync.aligned.m16n8k8.row.col.f32.tf32.tf32.f32 "
        "{%0,%1,%2,%3}, {%4,%5,%6,%7}, {%8,%9}, {%10,%11,%12,%13};"
        : "=f"(d[0]), "=f"(d[1]), "=f"(d[2]), "=f"(d[3])
        : "r"(a[0]), "r"(a[1]), "r"(a[2]), "r"(a[3]),
          "r"(b[0]), "r"(b[1]),
          "f"(c[0]), "f"(c[1]), "f"(c[2]), "f"(c[3]));
}

__device__ __forceinline__ void cp_async16(uint32_t saddr, const void* gptr) {
    asm volatile("cp.async.cg.shared.global [%0], [%1], 16;" :: "r"(saddr), "l"(gptr));
}
__device__ __forceinline__ void cp_commit() {
    asm volatile("cp.async.commit_group;" ::: "memory");
}
__device__ __forceinline__ void cp_wait1() {
    asm volatile("cp.async.wait_group 1;" ::: "memory");
}
__device__ __forceinline__ void cp_wait0() {
    asm volatile("cp.async.wait_group 0;" ::: "memory");
}

// ---------------- fused tf32 pre-conversion: x + all 4 weight matrices in ONE launch ----------------
#define NX (MTOT*DMODEL)
#define NW (DMODEL*DMODEL)
__global__ void tf32_convert_all_kernel(const float* __restrict__ x,
                                        const float* __restrict__ Wq,
                                        const float* __restrict__ Wk,
                                        const float* __restrict__ Wv,
                                        const float* __restrict__ Wo) {
    int total = NX + 4 * NW;
    int stride = gridDim.x * blockDim.x;
    for (int i = blockIdx.x * blockDim.x + threadIdx.x; i < total; i += stride) {
        if (i < NX) {
            g_xt[i] = __uint_as_float(to_tf32(x[i]));
        } else {
            int j = i - NX;
            int wsel = j / NW;
            int off  = j - wsel * NW;
            const float* src = (wsel == 0) ? Wq : (wsel == 1) ? Wk : (wsel == 2) ? Wv : Wo;
            float*       dst = (wsel == 0) ? g_wq : (wsel == 1) ? g_wk : (wsel == 2) ? g_wv : g_wo;
            dst[off] = __uint_as_float(to_tf32(src[off]));
        }
    }
}

// ---------------- tf32 tensor-core GEMM, cp.async double-buffered ----------------
// cvt_out=1: outputs tf32-rounded AND written at ctx-sorted row position inv[row]
// (row-permuted scatter; each row write remains fully coalesced).
#define GROW 36
#define GBUF (128*GROW)
__global__ __launch_bounds__(256, 2) void gemm_tc_kernel(
    const float* __restrict__ A,
    const float* __restrict__ W0, const float* __restrict__ b0, float* __restrict__ C0,
    const float* __restrict__ W1, const float* __restrict__ b1, float* __restrict__ C1,
    const float* __restrict__ W2, const float* __restrict__ b2, float* __restrict__ C2,
    int cvt_out)
{
    extern __shared__ float sm[];
    float* As = sm;               // [2][128][GROW]
    float* Bs = sm + 2 * GBUF;    // [2][128][GROW]

    int z = blockIdx.z;
    const float* W    = (z == 0) ? W0 : (z == 1) ? W1 : W2;
    const float* bias = (z == 0) ? b0 : (z == 1) ? b1 : b2;
    float*       C    = (z == 0) ? C0 : (z == 1) ? C1 : C2;

    int t    = threadIdx.x;
    int lane = t & 31;
    int warp = t >> 5;
    int g    = lane >> 2;
    int tq   = lane & 3;
    int wm   = (warp & 3) * 32;
    int wn   = (warp >> 2) * 64;
    int m0   = blockIdx.y * 128;
    int n0   = blockIdx.x * 128;

    float acc[2][8][4];
#pragma unroll
    for (int mt = 0; mt < 2; mt++)
#pragma unroll
        for (int nt = 0; nt < 8; nt++)
#pragma unroll
            for (int c = 0; c < 4; c++) acc[mt][nt][c] = 0.f;

    uint32_t as_s = (uint32_t)__cvta_generic_to_shared(As);
    uint32_t bs_s = (uint32_t)__cvta_generic_to_shared(Bs);

    auto stage = [&](int buf, int k0) {
        uint32_t bo = (uint32_t)buf * GBUF * 4;
#pragma unroll
        for (int u = 0; u < 4; u++) {
            int c = t + 256 * u;
            int row = c >> 3, c16 = c & 7;
            uint32_t soff = bo + (uint32_t)(row * GROW + c16 * 4) * 4;
            cp_async16(as_s + soff, &A[(size_t)(m0 + row) * DMODEL + k0 + c16 * 4]);
            cp_async16(bs_s + soff, &W[(size_t)(n0 + row) * DMODEL + k0 + c16 * 4]);
        }
        cp_commit();
    };

    stage(0, 0);

    const int NI = DMODEL / 32;   // 24
    for (int iter = 0; iter < NI; iter++) {
        int buf = iter & 1;
        if (iter + 1 < NI) {
            stage(buf ^ 1, (iter + 1) * 32);
            cp_wait1();
        } else {
            cp_wait0();
        }
        __syncthreads();

        const float* A2 = As + buf * GBUF;
        const float* B2 = Bs + buf * GBUF;

#pragma unroll
        for (int kk = 0; kk < 4; kk++) {
            int kb = kk * 8;
            uint32_t af[2][4];
#pragma unroll
            for (int mt = 0; mt < 2; mt++) {
                int rb = wm + mt * 16;
                af[mt][0] = __float_as_uint(A2[(rb + g    ) * GROW + kb + tq    ]);
                af[mt][1] = __float_as_uint(A2[(rb + g + 8) * GROW + kb + tq    ]);
                af[mt][2] = __float_as_uint(A2[(rb + g    ) * GROW + kb + tq + 4]);
                af[mt][3] = __float_as_uint(A2[(rb + g + 8) * GROW + kb + tq + 4]);
            }
#pragma unroll
            for (int nt = 0; nt < 8; nt++) {
                uint32_t bf[2];
                bf[0] = __float_as_uint(B2[(wn + nt*8 + g) * GROW + kb + tq    ]);
                bf[1] = __float_as_uint(B2[(wn + nt*8 + g) * GROW + kb + tq + 4]);
                mma_tf32(acc[0][nt], af[0], bf, acc[0][nt]);
                mma_tf32(acc[1][nt], af[1], bf, acc[1][nt]);
            }
        }
        __syncthreads();
    }

#pragma unroll
    for (int mt = 0; mt < 2; mt++) {
        int row = m0 + wm + mt * 16 + g;
        int r0 = row, r1 = row + 8;
        if (cvt_out) {   // ctx-sorted scatter (rows stay within batch: SEQ-aligned tiles)
            r0 = (row & ~(SEQ - 1)) + g_inv[row];
            r1 = ((row + 8) & ~(SEQ - 1)) + g_inv[row + 8];
        }
#pragma unroll
        for (int nt = 0; nt < 8; nt++) {
            int col = n0 + wn + nt * 8 + 2 * tq;
            float b0v = bias[col], b1v = bias[col + 1];
            float v00 = acc[mt][nt][0] + b0v, v01 = acc[mt][nt][1] + b1v;
            float v10 = acc[mt][nt][2] + b0v, v11 = acc[mt][nt][3] + b1v;
            if (cvt_out) {
                v00 = __uint_as_float(to_tf32(v00)); v01 = __uint_as_float(to_tf32(v01));
                v10 = __uint_as_float(to_tf32(v10)); v11 = __uint_as_float(to_tf32(v11));
            }
            *(float2*)&C[(size_t)r0 * DMODEL + col] = make_float2(v00, v01);
            *(float2*)&C[(size_t)r1 * DMODEL + col] = make_float2(v10, v11);
        }
    }
}

// ---------------- Flash attention on ctx-sorted Q/K/V ----------------
// Keys sorted ctx-first per batch: all-ctx CTAs iterate only ceil(nctx/32) tiles.
// Mask from index compare (key >= nctx && query is ctx); skipped for tiles fully
// inside the ctx region. Output scattered back to original rows via perm.
__global__ __launch_bounds__(256, 2) void attn_tc_kernel() {
    __shared__ __align__(16) float Ksf[2][32][68];
    __shared__ __align__(16) float Vsf[2][32][68];
    __shared__ uint32_t Ps[8][16][36];

    int t    = threadIdx.x;
    int lane = t & 31;
    int w    = t >> 5;
    int g    = lane >> 2;
    int tq   = lane & 3;

    int b  = blockIdx.z;
    int h  = blockIdx.y;
    int qrow = blockIdx.x * 128 + w * 16;     // NEW (sorted) position
    int nctx = g_nctx[b];

    // tile count: all-ctx CTA -> only the ctx key region
    bool all_ctx = (blockIdx.x * 128 + 128) <= nctx;
    int NT_cta = all_ctx ? (nctx + 31) / 32 : (SEQ / 32);

    // Q fragments (tf32-rounded already; *0.125f exact on tf32)
    uint32_t qa[8][4];
    {
        const float* qb = &g_q[(size_t)(b * SEQ + qrow) * DMODEL + h * HDIM];
#pragma unroll
        for (int ks = 0; ks < 8; ks++) {
            qa[ks][0] = __float_as_uint(qb[(size_t)g       * DMODEL + ks*8 + tq    ] * 0.125f);
            qa[ks][1] = __float_as_uint(qb[(size_t)(g + 8) * DMODEL + ks*8 + tq    ] * 0.125f);
            qa[ks][2] = __float_as_uint(qb[(size_t)g       * DMODEL + ks*8 + tq + 4] * 0.125f);
            qa[ks][3] = __float_as_uint(qb[(size_t)(g + 8) * DMODEL + ks*8 + tq + 4] * 0.125f);
        }
    }
    float rf0 = (qrow + g     < nctx) ? 1.f : 0.f;   // ctx-row flags (sorted order)
    float rf1 = (qrow + g + 8 < nctx) ? 1.f : 0.f;

    float o[8][4];
#pragma unroll
    for (int nt = 0; nt < 8; nt++)
#pragma unroll
        for (int c = 0; c < 4; c++) o[nt][c] = 0.f;
    float m0r = -1e30f, m1r = -1e30f, l0 = 0.f, l1 = 0.f;

    int key0 = t >> 4,         c40 = t & 15;
    int key1 = (t + 256) >> 4, c41 = (t + 256) & 15;
    size_t sbase = (size_t)(b * SEQ) * DMODEL + h * HDIM;

    uint32_t ks_s = (uint32_t)__cvta_generic_to_shared(&Ksf[0][0][0]);
    uint32_t vs_s = (uint32_t)__cvta_generic_to_shared(&Vsf[0][0][0]);

    auto stage = [&](int buf, int kt) {
        size_t nb = sbase + (size_t)kt * DMODEL;
        uint32_t bo = (uint32_t)buf * (32 * 68 * 4);
        cp_async16(ks_s + bo + (key0 * 68 + c40 * 4) * 4, &g_k[nb + (size_t)key0 * DMODEL + c40 * 4]);
        cp_async16(ks_s + bo + (key1 * 68 + c41 * 4) * 4, &g_k[nb + (size_t)key1 * DMODEL + c41 * 4]);
        cp_async16(vs_s + bo + (key0 * 68 + c40 * 4) * 4, &g_v[nb + (size_t)key0 * DMODEL + c40 * 4]);
        cp_async16(vs_s + bo + (key1 * 68 + c41 * 4) * 4, &g_v[nb + (size_t)key1 * DMODEL + c41 * 4]);
        cp_commit();
    };

    stage(0, 0);

    for (int tile = 0; tile < NT_cta; tile++) {
        int buf = tile & 1;
        if (tile + 1 < NT_cta) {
            stage(buf ^ 1, (tile + 1) * 32);
            cp_wait1();
        } else {
            cp_wait0();
        }
        __syncthreads();

        const float (*Kt)[68] = Ksf[buf];
        const float (*Vt)[68] = Vsf[buf];
        int k0b = tile * 32;

        // ---- S = Q K^T (16 x 32) ----
        float sacc[4][4];
#pragma unroll
        for (int nt = 0; nt < 4; nt++)
#pragma unroll
            for (int c = 0; c < 4; c++) sacc[nt][c] = 0.f;
#pragma unroll
        for (int ks = 0; ks < 8; ks++) {
#pragma unroll
            for (int nt = 0; nt < 4; nt++) {
                uint32_t bf[2];
                bf[0] = __float_as_uint(Kt[nt*8 + g][ks*8 + tq    ]);
                bf[1] = __float_as_uint(Kt[nt*8 + g][ks*8 + tq + 4]);
                mma_tf32(sacc[nt], qa[ks], bf, sacc[nt]);
            }
        }

        // ---- mask (additive -1e30; only when tile straddles/exceeds ctx region) ----
        if (k0b + 32 > nctx) {
#pragma unroll
            for (int nt = 0; nt < 4; nt++) {
                int col = k0b + nt*8 + 2*tq;
                float k0m = (col     < nctx) ? 0.f : -1e30f;
                float k1m = (col + 1 < nctx) ? 0.f : -1e30f;
                sacc[nt][0] = fmaf(rf0, k0m, sacc[nt][0]);
                sacc[nt][1] = fmaf(rf0, k1m, sacc[nt][1]);
                sacc[nt][2] = fmaf(rf1, k0m, sacc[nt][2]);
                sacc[nt][3] = fmaf(rf1, k1m, sacc[nt][3]);
            }
        }

        // ---- online softmax (MUFU exps) ----
        float mx0 = -1e30f, mx1 = -1e30f;
#pragma unroll
        for (int nt = 0; nt < 4; nt++) {
            mx0 = fmaxf(mx0, fmaxf(sacc[nt][0], sacc[nt][1]));
            mx1 = fmaxf(mx1, fmaxf(sacc[nt][2], sacc[nt][3]));
        }
        mx0 = fmaxf(mx0, __shfl_xor_sync(0xffffffffu, mx0, 1));
        mx0 = fmaxf(mx0, __shfl_xor_sync(0xffffffffu, mx0, 2));
        mx1 = fmaxf(mx1, __shfl_xor_sync(0xffffffffu, mx1, 1));
        mx1 = fmaxf(mx1, __shfl_xor_sync(0xffffffffu, mx1, 2));

        float mn0 = fmaxf(m0r, mx0), mn1 = fmaxf(m1r, mx1);
        float corr0 = __expf(m0r - mn0), corr1 = __expf(m1r - mn1);
        m0r = mn0; m1r = mn1;

        float rs0 = 0.f, rs1 = 0.f;
        __syncwarp();
#pragma unroll
        for (int nt = 0; nt < 4; nt++) {
            int col = nt*8 + 2*tq;
            float p00 = __expf(sacc[nt][0] - mn0);
            float p01 = __expf(sacc[nt][1] - mn0);
            float p10 = __expf(sacc[nt][2] - mn1);
            float p11 = __expf(sacc[nt][3] - mn1);
            rs0 += p00 + p01; rs1 += p10 + p11;
            Ps[w][g    ][col    ] = to_tf32(p00);
            Ps[w][g    ][col + 1] = to_tf32(p01);
            Ps[w][g + 8][col    ] = to_tf32(p10);
            Ps[w][g + 8][col + 1] = to_tf32(p11);
        }
        rs0 += __shfl_xor_sync(0xffffffffu, rs0, 1);
        rs0 += __shfl_xor_sync(0xffffffffu, rs0, 2);
        rs1 += __shfl_xor_sync(0xffffffffu, rs1, 1);
        rs1 += __shfl_xor_sync(0xffffffffu, rs1, 2);
        l0 = l0 * corr0 + rs0;
        l1 = l1 * corr1 + rs1;

#pragma unroll
        for (int nt = 0; nt < 8; nt++) {
            o[nt][0] *= corr0; o[nt][1] *= corr0;
            o[nt][2] *= corr1; o[nt][3] *= corr1;
        }
        __syncwarp();

        // ---- O += P V  (16 x 64, k=32) ----
#pragma unroll
        for (int ks = 0; ks < 4; ks++) {
            uint32_t ap[4];
            ap[0] = Ps[w][g    ][ks*8 + tq    ];
            ap[1] = Ps[w][g + 8][ks*8 + tq    ];
            ap[2] = Ps[w][g    ][ks*8 + tq + 4];
            ap[3] = Ps[w][g + 8][ks*8 + tq + 4];
#pragma unroll
            for (int nt = 0; nt < 8; nt++) {
                uint32_t bf[2];
                bf[0] = __float_as_uint(Vt[ks*8 + tq    ][nt*8 + g]);
                bf[1] = __float_as_uint(Vt[ks*8 + tq + 4][nt*8 + g]);
                mma_tf32(o[nt], ap, bf, o[nt]);
            }
        }
        __syncthreads();
    }

    // ---- normalize + write back to ORIGINAL rows (tf32-rounded; O GEMM input) ----
    float inv0 = 1.f / l0, inv1 = 1.f / l1;
    int orow0 = g_perm[b * SEQ + qrow + g    ];
    int orow1 = g_perm[b * SEQ + qrow + g + 8];
    float* ob0 = &g_att[((size_t)b * SEQ + orow0) * DMODEL + h * HDIM];
    float* ob1 = &g_att[((size_t)b * SEQ + orow1) * DMODEL + h * HDIM];
#pragma unroll
    for (int nt = 0; nt < 8; nt++) {
        int col = nt*8 + 2*tq;
        *(float2*)&ob0[col] = make_float2(__uint_as_float(to_tf32(o[nt][0] * inv0)),
                                          __uint_as_float(to_tf32(o[nt][1] * inv0)));
        *(float2*)&ob1[col] = make_float2(__uint_as_float(to_tf32(o[nt][2] * inv1)),
                                          __uint_as_float(to_tf32(o[nt][3] * inv1)));
    }
}

// ---------------- launch ----------------
extern "C" void kernel_launch(void* const* d_in, const int* in_sizes, int n_in,
                              void* d_out, int out_size) {
    const float* x   = (const float*)d_in[0];
    const void*  ctx = d_in[1];
    const float* Wq  = (const float*)d_in[2];
    const float* bq  = (const float*)d_in[3];
    const float* Wk  = (const float*)d_in[4];
    const float* bk  = (const float*)d_in[5];
    const float* Wv  = (const float*)d_in[6];
    const float* bv  = (const float*)d_in[7];
    const float* Wo  = (const float*)d_in[8];
    const float* bo  = (const float*)d_in[9];
    float* out = (float*)d_out;

    float *qb, *kb, *vb, *ab, *xt, *wq, *wk, *wv, *wo;
    cudaGetSymbolAddress((void**)&qb, g_q);
    cudaGetSymbolAddress((void**)&kb, g_k);
    cudaGetSymbolAddress((void**)&vb, g_v);
    cudaGetSymbolAddress((void**)&ab, g_att);
    cudaGetSymbolAddress((void**)&xt, g_xt);
    cudaGetSymbolAddress((void**)&wq, g_wq);
    cudaGetSymbolAddress((void**)&wk, g_wk);
    cudaGetSymbolAddress((void**)&wv, g_wv);
    cudaGetSymbolAddress((void**)&wo, g_wo);

    static bool attr_set = false;
    if (!attr_set) {
        cudaFuncSetAttribute(gemm_tc_kernel, cudaFuncAttributeMaxDynamicSharedMemorySize,
                             4 * GBUF * (int)sizeof(float));
        attr_set = true;
    }

    detect_dtype_kernel<<<1, 1024>>>((const unsigned char*)ctx, MTOT);
    ctx_convert_kernel<<<(MTOT + 255) / 256, 256>>>(ctx, MTOT);
    build_perm_kernel<<<BATCH, 256>>>();

    tf32_convert_all_kernel<<<1184, 256>>>(x, Wq, Wk, Wv, Wo);

    int smem = 4 * GBUF * (int)sizeof(float);   // 73728 B

    dim3 gqkv(DMODEL / 128, MTOT / 128, 3);
    gemm_tc_kernel<<<gqkv, 256, smem>>>(xt, wq, bq, qb, wk, bk, kb, wv, bv, vb, 1);

    attn_tc_kernel<<<dim3(SEQ / 128, NHEAD, BATCH), 256>>>();

    dim3 go(DMODEL / 128, MTOT / 128, 1);
    gemm_tc_kernel<<<go, 256, smem>>>(ab, wo, bo, out, wo, bo, out, wo, bo, out, 0);
}

// round 13
// speedup vs baseline: 1.7764x; 1.4033x over previous
#include <cuda_runtime.h>
#include <cuda_fp16.h>
#include <math.h>
#include <stdint.h>

#define BATCH  4
#define SEQ    2048
#define DMODEL 768
#define NHEAD  12
#define HDIM   64
#define MTOT   (BATCH*SEQ)

// ---------------- scratch (static device globals; no allocs allowed) ----------------
__device__ __half g_qh[MTOT*DMODEL];   // Q (x Wq^T + b) * 0.125, half, ctx-sorted rows
__device__ __half g_kh[MTOT*DMODEL];   // K, half, ctx-sorted rows
__device__ __half g_vh[MTOT*DMODEL];   // V^T, half: [b,h][dim][key(sorted)]
__device__ float g_att[MTOT*DMODEL];   // ORIGINAL row order (consumed by O GEMM)
__device__ float g_xt[MTOT*DMODEL];    // x, tf32-rounded
__device__ float g_wq[DMODEL*DMODEL];  // weights, tf32-rounded
__device__ float g_wk[DMODEL*DMODEL];
__device__ float g_wv[DMODEL*DMODEL];
__device__ float g_wo[DMODEL*DMODEL];
__device__ unsigned char g_ctx[MTOT];
__device__ int g_perm[MTOT];           // perm[new] = old  (per batch, ctx rows first)
__device__ int g_inv[MTOT];            // inv[old] = new
__device__ int g_nctx[BATCH];
__device__ int g_is_byte;

// ---------------- is_context dtype detection ----------------
__global__ void detect_dtype_kernel(const unsigned char* __restrict__ p, int nbytes) {
    __shared__ int found;
    if (threadIdx.x == 0) found = 0;
    __syncthreads();
    int loc = 0;
    for (int i = threadIdx.x; i < nbytes; i += blockDim.x)
        if ((i & 3) == 1 && p[i] != 0) loc = 1;
    if (loc) atomicOr(&found, 1);
    __syncthreads();
    if (threadIdx.x == 0) g_is_byte = found;
}

__global__ void ctx_convert_kernel(const void* __restrict__ p, int n) {
    int i = blockIdx.x * blockDim.x + threadIdx.x;
    if (i >= n) return;
    int v;
    if (g_is_byte) v = ((const unsigned char*)p)[i];
    else           v = ((const int*)p)[i];
    g_ctx[i] = v ? 1 : 0;
}

// ---------------- stable partition (ctx first) per batch: block scan ----------------
__global__ void build_perm_kernel() {
    __shared__ int partial[256];
    int b = blockIdx.x, t = threadIdx.x;
    int flags[8];
    int cnt = 0;
#pragma unroll
    for (int i = 0; i < 8; i++) {
        flags[i] = g_ctx[b * SEQ + t * 8 + i];
        cnt += flags[i];
    }
    partial[t] = cnt;
    __syncthreads();
    for (int off = 1; off < 256; off <<= 1) {
        int v = (t >= off) ? partial[t - off] : 0;
        __syncthreads();
        partial[t] += v;
        __syncthreads();
    }
    int total = partial[255];
    int run = partial[t] - cnt;
#pragma unroll
    for (int i = 0; i < 8; i++) {
        int old = t * 8 + i;
        int newpos;
        if (flags[i]) { newpos = run; run++; }
        else          { newpos = total + (old - run); }
        g_perm[b * SEQ + newpos] = old;
        g_inv[b * SEQ + old] = newpos;
    }
    if (t == 0) g_nctx[b] = total;
}

// ---------------- helpers ----------------
__device__ __forceinline__ uint32_t to_tf32(float x) {
    uint32_t r;
    asm("cvt.rna.tf32.f32 %0, %1;" : "=r"(r) : "f"(x));
    return r;
}

__device__ __forceinline__ void mma_tf32(float* d, const uint32_t* a, const uint32_t* b, const float* c) {
    asm volatile(
        "mma.sync.aligned.m16n8k8.row.col.f32.tf32.tf32.f32 "
        "{%0,%1,%2,%3}, {%4,%5,%6,%7}, {%8,%9}, {%10,%11,%12,%13};"
        : "=f"(d[0]), "=f"(d[1]), "=f"(d[2]), "=f"(d[3])
        : "r"(a[0]), "r"(a[1]), "r"(a[2]), "r"(a[3]),
          "r"(b[0]), "r"(b[1]),
          "f"(c[0]), "f"(c[1]), "f"(c[2]), "f"(c[3]));
}

// fp16 mma, fp32 accumulate: D(16x8) = A(16x16,row) * B(16x8,col) + C
__device__ __forceinline__ void mma_f16(float* d, const uint32_t* a, const uint32_t* b, const float* c) {
    asm volatile(
        "mma.sync.aligned.m16n8k16.row.col.f32.f16.f16.f32 "
        "{%0,%1,%2,%3}, {%4,%5,%6,%7}, {%8,%9}, {%10,%11,%12,%13};"
        : "=f"(d[0]), "=f"(d[1]), "=f"(d[2]), "=f"(d[3])
        : "r"(a[0]), "r"(a[1]), "r"(a[2]), "r"(a[3]),
          "r"(b[0]), "r"(b[1]),
          "f"(c[0]), "f"(c[1]), "f"(c[2]), "f"(c[3]));
}

__device__ __forceinline__ uint32_t pack_h2(float lo, float hi) {
    __half2 h = __floats2half2_rn(lo, hi);
    return *(uint32_t*)&h;
}

__device__ __forceinline__ void cp_async16(uint32_t saddr, const void* gptr) {
    asm volatile("cp.async.cg.shared.global [%0], [%1], 16;" :: "r"(saddr), "l"(gptr));
}
__device__ __forceinline__ void cp_commit() {
    asm volatile("cp.async.commit_group;" ::: "memory");
}
__device__ __forceinline__ void cp_wait1() {
    asm volatile("cp.async.wait_group 1;" ::: "memory");
}
__device__ __forceinline__ void cp_wait0() {
    asm volatile("cp.async.wait_group 0;" ::: "memory");
}

// ---------------- fused tf32 pre-conversion ----------------
#define NX (MTOT*DMODEL)
#define NW (DMODEL*DMODEL)
__global__ void tf32_convert_all_kernel(const float* __restrict__ x,
                                        const float* __restrict__ Wq,
                                        const float* __restrict__ Wk,
                                        const float* __restrict__ Wv,
                                        const float* __restrict__ Wo) {
    int total = NX + 4 * NW;
    int stride = gridDim.x * blockDim.x;
    for (int i = blockIdx.x * blockDim.x + threadIdx.x; i < total; i += stride) {
        if (i < NX) {
            g_xt[i] = __uint_as_float(to_tf32(x[i]));
        } else {
            int j = i - NX;
            int wsel = j / NW;
            int off  = j - wsel * NW;
            const float* src = (wsel == 0) ? Wq : (wsel == 1) ? Wk : (wsel == 2) ? Wv : Wo;
            float*       dst = (wsel == 0) ? g_wq : (wsel == 1) ? g_wk : (wsel == 2) ? g_wv : g_wo;
            dst[off] = __uint_as_float(to_tf32(src[off]));
        }
    }
}

// ---------------- tf32 tensor-core GEMM, cp.async double-buffered ----------------
// cvt_out=0: fp32 natural output (O projection).
// cvt_out=1: fused QKV. z=0 -> Q half * 0.125, ctx-sorted rows; z=1 -> K half,
// ctx-sorted rows; z=2 -> V^T half, [b,h][dim][key(sorted)].
#define GROW 36
#define GBUF (128*GROW)
__global__ __launch_bounds__(256, 2) void gemm_tc_kernel(
    const float* __restrict__ A,
    const float* __restrict__ W0, const float* __restrict__ b0, void* __restrict__ C0,
    const float* __restrict__ W1, const float* __restrict__ b1, void* __restrict__ C1,
    const float* __restrict__ W2, const float* __restrict__ b2, void* __restrict__ C2,
    int cvt_out)
{
    extern __shared__ float sm[];
    float* As = sm;               // [2][128][GROW]
    float* Bs = sm + 2 * GBUF;    // [2][128][GROW]

    int z = blockIdx.z;
    const float* W    = (z == 0) ? W0 : (z == 1) ? W1 : W2;
    const float* bias = (z == 0) ? b0 : (z == 1) ? b1 : b2;
    void*        C    = (z == 0) ? C0 : (z == 1) ? C1 : C2;

    int t    = threadIdx.x;
    int lane = t & 31;
    int warp = t >> 5;
    int g    = lane >> 2;
    int tq   = lane & 3;
    int wm   = (warp & 3) * 32;
    int wn   = (warp >> 2) * 64;
    int m0   = blockIdx.y * 128;
    int n0   = blockIdx.x * 128;

    float acc[2][8][4];
#pragma unroll
    for (int mt = 0; mt < 2; mt++)
#pragma unroll
        for (int nt = 0; nt < 8; nt++)
#pragma unroll
            for (int c = 0; c < 4; c++) acc[mt][nt][c] = 0.f;

    uint32_t as_s = (uint32_t)__cvta_generic_to_shared(As);
    uint32_t bs_s = (uint32_t)__cvta_generic_to_shared(Bs);

    auto stage = [&](int buf, int k0) {
        uint32_t bo = (uint32_t)buf * GBUF * 4;
#pragma unroll
        for (int u = 0; u < 4; u++) {
            int c = t + 256 * u;
            int row = c >> 3, c16 = c & 7;
            uint32_t soff = bo + (uint32_t)(row * GROW + c16 * 4) * 4;
            cp_async16(as_s + soff, &A[(size_t)(m0 + row) * DMODEL + k0 + c16 * 4]);
            cp_async16(bs_s + soff, &W[(size_t)(n0 + row) * DMODEL + k0 + c16 * 4]);
        }
        cp_commit();
    };

    stage(0, 0);

    const int NI = DMODEL / 32;   // 24
    for (int iter = 0; iter < NI; iter++) {
        int buf = iter & 1;
        if (iter + 1 < NI) {
            stage(buf ^ 1, (iter + 1) * 32);
            cp_wait1();
        } else {
            cp_wait0();
        }
        __syncthreads();

        const float* A2 = As + buf * GBUF;
        const float* B2 = Bs + buf * GBUF;

#pragma unroll
        for (int kk = 0; kk < 4; kk++) {
            int kb = kk * 8;
            uint32_t af[2][4];
#pragma unroll
            for (int mt = 0; mt < 2; mt++) {
                int rb = wm + mt * 16;
                af[mt][0] = __float_as_uint(A2[(rb + g    ) * GROW + kb + tq    ]);
                af[mt][1] = __float_as_uint(A2[(rb + g + 8) * GROW + kb + tq    ]);
                af[mt][2] = __float_as_uint(A2[(rb + g    ) * GROW + kb + tq + 4]);
                af[mt][3] = __float_as_uint(A2[(rb + g + 8) * GROW + kb + tq + 4]);
            }
#pragma unroll
            for (int nt = 0; nt < 8; nt++) {
                uint32_t bf[2];
                bf[0] = __float_as_uint(B2[(wn + nt*8 + g) * GROW + kb + tq    ]);
                bf[1] = __float_as_uint(B2[(wn + nt*8 + g) * GROW + kb + tq + 4]);
                mma_tf32(acc[0][nt], af[0], bf, acc[0][nt]);
                mma_tf32(acc[1][nt], af[1], bf, acc[1][nt]);
            }
        }
        __syncthreads();
    }

#pragma unroll
    for (int mt = 0; mt < 2; mt++) {
        int row = m0 + wm + mt * 16 + g;
        int r0 = row, r1 = row + 8;
        if (cvt_out) {   // ctx-sorted scatter (rows stay within batch: SEQ-aligned tiles)
            r0 = (row & ~(SEQ - 1)) + g_inv[row];
            r1 = ((row + 8) & ~(SEQ - 1)) + g_inv[row + 8];
        }
#pragma unroll
        for (int nt = 0; nt < 8; nt++) {
            int col = n0 + wn + nt * 8 + 2 * tq;
            float b0v = bias[col], b1v = bias[col + 1];
            float v00 = acc[mt][nt][0] + b0v, v01 = acc[mt][nt][1] + b1v;
            float v10 = acc[mt][nt][2] + b0v, v11 = acc[mt][nt][3] + b1v;
            if (!cvt_out) {
                float* Cf = (float*)C;
                *(float2*)&Cf[(size_t)r0 * DMODEL + col] = make_float2(v00, v01);
                *(float2*)&Cf[(size_t)r1 * DMODEL + col] = make_float2(v10, v11);
            } else if (z <= 1) {
                // Q (scaled) / K: half2, sorted rows, natural [row][dim]
                float s = (z == 0) ? 0.125f : 1.0f;
                __half* Ch = (__half*)C;
                uint32_t p0 = pack_h2(v00 * s, v01 * s);
                uint32_t p1 = pack_h2(v10 * s, v11 * s);
                *(uint32_t*)&Ch[(size_t)r0 * DMODEL + col] = p0;
                *(uint32_t*)&Ch[(size_t)r1 * DMODEL + col] = p1;
            } else {
                // V^T half: [b,h][dim][key]; key = sorted row within batch
                __half* Vh = (__half*)C;
                int hh = col >> 6, d = col & 63;
                int b0i = r0 >> 11, k0i = r0 & (SEQ - 1);
                int b1i = r1 >> 11, k1i = r1 & (SEQ - 1);
                size_t base0 = (((size_t)b0i * NHEAD + hh) * HDIM + d) * SEQ;
                size_t base1 = (((size_t)b1i * NHEAD + hh) * HDIM + d) * SEQ;
                Vh[base0 + k0i]       = __float2half_rn(v00);
                Vh[base0 + SEQ + k0i] = __float2half_rn(v01);   // d+1
                Vh[base1 + k1i]       = __float2half_rn(v10);
                Vh[base1 + SEQ + k1i] = __float2half_rn(v11);
            }
        }
    }
}

// ---------------- Flash attention: fp16 m16n8k16, ctx-sorted, cp.async 2-buf ----------------
// K tile [32 keys][64 dims] half (row stride 72 halves = 36 words, conflict-free);
// V^T tile [64 dims][32 keys] half (row stride 40 halves = 20 words);
// P tile half2-packed (row stride 20 words). All fragment regs = single LDS.32.
__global__ __launch_bounds__(256, 2) void attn_tc_kernel() {
    __shared__ __align__(16) uint32_t Ksw[2][32][36];
    __shared__ __align__(16) uint32_t Vtw[2][64][20];
    __shared__ __align__(16) uint32_t Ps[8][16][20];

    int t    = threadIdx.x;
    int lane = t & 31;
    int w    = t >> 5;
    int g    = lane >> 2;
    int tq   = lane & 3;

    int b  = blockIdx.z;
    int h  = blockIdx.y;
    int qrow = blockIdx.x * 128 + w * 16;     // sorted position
    int nctx = g_nctx[b];

    bool all_ctx = (blockIdx.x * 128 + 128) <= nctx;
    int NT_cta = all_ctx ? (nctx + 31) / 32 : (SEQ / 32);

    // Q fragments (half, pre-scaled by 0.125 in the GEMM): 4 ksteps x 4 regs,
    // every reg a contiguous half2 -> plain 32-bit loads.
    uint32_t qa[4][4];
    {
        const __half* qb = g_qh + (size_t)(b * SEQ + qrow) * DMODEL + h * HDIM;
#pragma unroll
        for (int kst = 0; kst < 4; kst++) {
            qa[kst][0] = *(const uint32_t*)&qb[(size_t)g       * DMODEL + kst*16 + 2*tq    ];
            qa[kst][1] = *(const uint32_t*)&qb[(size_t)(g + 8) * DMODEL + kst*16 + 2*tq    ];
            qa[kst][2] = *(const uint32_t*)&qb[(size_t)g       * DMODEL + kst*16 + 2*tq + 8];
            qa[kst][3] = *(const uint32_t*)&qb[(size_t)(g + 8) * DMODEL + kst*16 + 2*tq + 8];
        }
    }
    float rf0 = (qrow + g     < nctx) ? 1.f : 0.f;
    float rf1 = (qrow + g + 8 < nctx) ? 1.f : 0.f;

    float o[8][4];
#pragma unroll
    for (int nt = 0; nt < 8; nt++)
#pragma unroll
        for (int c = 0; c < 4; c++) o[nt][c] = 0.f;
    float m0r = -1e30f, m1r = -1e30f, l0 = 0.f, l1 = 0.f;

    // staging geometry: K: 256 chunks of 16B (key=t>>3, c=t&7); V^T: 256 chunks (dim=t>>2, c=t&3)
    int kkey = t >> 3, kc = t & 7;
    int vdim = t >> 2, vc = t & 3;
    const __half* kb_g = g_kh + (size_t)(b * SEQ) * DMODEL + h * HDIM;
    const __half* vb_g = g_vh + ((size_t)b * NHEAD + h) * HDIM * SEQ;

    uint32_t ks_s = (uint32_t)__cvta_generic_to_shared(&Ksw[0][0][0]);
    uint32_t vs_s = (uint32_t)__cvta_generic_to_shared(&Vtw[0][0][0]);
    const uint32_t KBUF = 32 * 36 * 4;
    const uint32_t VBUF = 64 * 20 * 4;

    auto stage = [&](int buf, int kt) {
        cp_async16(ks_s + buf * KBUF + (uint32_t)(kkey * 36 + kc * 4) * 4,
                   kb_g + (size_t)(kt + kkey) * DMODEL + kc * 8);
        cp_async16(vs_s + buf * VBUF + (uint32_t)(vdim * 20 + vc * 4) * 4,
                   vb_g + (size_t)vdim * SEQ + kt + vc * 8);
        cp_commit();
    };

    stage(0, 0);

    for (int tile = 0; tile < NT_cta; tile++) {
        int buf = tile & 1;
        if (tile + 1 < NT_cta) {
            stage(buf ^ 1, (tile + 1) * 32);
            cp_wait1();
        } else {
            cp_wait0();
        }
        __syncthreads();

        int k0b = tile * 32;

        // ---- S = Q K^T (16 x 32): 16 f16 mmas, fragment regs via single LDS.32 ----
        float sacc[4][4];
#pragma unroll
        for (int nt = 0; nt < 4; nt++)
#pragma unroll
            for (int c = 0; c < 4; c++) sacc[nt][c] = 0.f;
#pragma unroll
        for (int kst = 0; kst < 4; kst++) {
#pragma unroll
            for (int nt = 0; nt < 4; nt++) {
                uint32_t bf[2];
                bf[0] = Ksw[buf][nt*8 + g][kst*8 + tq    ];
                bf[1] = Ksw[buf][nt*8 + g][kst*8 + tq + 4];
                mma_f16(sacc[nt], qa[kst], bf, sacc[nt]);
            }
        }

        // ---- mask (additive -1e30; only when tile straddles/exceeds ctx region) ----
        if (k0b + 32 > nctx) {
#pragma unroll
            for (int nt = 0; nt < 4; nt++) {
                int col = k0b + nt*8 + 2*tq;
                float k0m = (col     < nctx) ? 0.f : -1e30f;
                float k1m = (col + 1 < nctx) ? 0.f : -1e30f;
                sacc[nt][0] = fmaf(rf0, k0m, sacc[nt][0]);
                sacc[nt][1] = fmaf(rf0, k1m, sacc[nt][1]);
                sacc[nt][2] = fmaf(rf1, k0m, sacc[nt][2]);
                sacc[nt][3] = fmaf(rf1, k1m, sacc[nt][3]);
            }
        }

        // ---- online softmax (MUFU exps) ----
        float mx0 = -1e30f, mx1 = -1e30f;
#pragma unroll
        for (int nt = 0; nt < 4; nt++) {
            mx0 = fmaxf(mx0, fmaxf(sacc[nt][0], sacc[nt][1]));
            mx1 = fmaxf(mx1, fmaxf(sacc[nt][2], sacc[nt][3]));
        }
        mx0 = fmaxf(mx0, __shfl_xor_sync(0xffffffffu, mx0, 1));
        mx0 = fmaxf(mx0, __shfl_xor_sync(0xffffffffu, mx0, 2));
        mx1 = fmaxf(mx1, __shfl_xor_sync(0xffffffffu, mx1, 1));
        mx1 = fmaxf(mx1, __shfl_xor_sync(0xffffffffu, mx1, 2));

        float mn0 = fmaxf(m0r, mx0), mn1 = fmaxf(m1r, mx1);
        float corr0 = __expf(m0r - mn0), corr1 = __expf(m1r - mn1);
        m0r = mn0; m1r = mn1;

        float rs0 = 0.f, rs1 = 0.f;
        __syncwarp();
        // P stored as half2 (cols 2tq, 2tq+1 packed): word index nt*4+tq
#pragma unroll
        for (int nt = 0; nt < 4; nt++) {
            float p00 = __expf(sacc[nt][0] - mn0);
            float p01 = __expf(sacc[nt][1] - mn0);
            float p10 = __expf(sacc[nt][2] - mn1);
            float p11 = __expf(sacc[nt][3] - mn1);
            rs0 += p00 + p01; rs1 += p10 + p11;
            int pw = nt*4 + tq;
            Ps[w][g    ][pw] = pack_h2(p00, p01);
            Ps[w][g + 8][pw] = pack_h2(p10, p11);
        }
        rs0 += __shfl_xor_sync(0xffffffffu, rs0, 1);
        rs0 += __shfl_xor_sync(0xffffffffu, rs0, 2);
        rs1 += __shfl_xor_sync(0xffffffffu, rs1, 1);
        rs1 += __shfl_xor_sync(0xffffffffu, rs1, 2);
        l0 = l0 * corr0 + rs0;
        l1 = l1 * corr1 + rs1;

#pragma unroll
        for (int nt = 0; nt < 8; nt++) {
            o[nt][0] *= corr0; o[nt][1] *= corr0;
            o[nt][2] *= corr1; o[nt][3] *= corr1;
        }
        __syncwarp();

        // ---- O += P V (16 x 64, k=32): 16 f16 mmas; V^T frags = single LDS.32 ----
#pragma unroll
        for (int c2 = 0; c2 < 2; c2++) {
            uint32_t ap[4];
            ap[0] = Ps[w][g    ][c2*8 + tq    ];
            ap[1] = Ps[w][g + 8][c2*8 + tq    ];
            ap[2] = Ps[w][g    ][c2*8 + tq + 4];
            ap[3] = Ps[w][g + 8][c2*8 + tq + 4];
#pragma unroll
            for (int nt = 0; nt < 8; nt++) {
                uint32_t bf[2];
                bf[0] = Vtw[buf][nt*8 + g][c2*8 + tq    ];
                bf[1] = Vtw[buf][nt*8 + g][c2*8 + tq + 4];
                mma_f16(o[nt], ap, bf, o[nt]);
            }
        }
        __syncthreads();
    }

    // ---- normalize + write back to ORIGINAL rows (tf32-rounded; O GEMM input) ----
    float inv0 = 1.f / l0, inv1 = 1.f / l1;
    int orow0 = g_perm[b * SEQ + qrow + g    ];
    int orow1 = g_perm[b * SEQ + qrow + g + 8];
    float* ob0 = &g_att[((size_t)b * SEQ + orow0) * DMODEL + h * HDIM];
    float* ob1 = &g_att[((size_t)b * SEQ + orow1) * DMODEL + h * HDIM];
#pragma unroll
    for (int nt = 0; nt < 8; nt++) {
        int col = nt*8 + 2*tq;
        *(float2*)&ob0[col] = make_float2(__uint_as_float(to_tf32(o[nt][0] * inv0)),
                                          __uint_as_float(to_tf32(o[nt][1] * inv0)));
        *(float2*)&ob1[col] = make_float2(__uint_as_float(to_tf32(o[nt][2] * inv1)),
                                          __uint_as_float(to_tf32(o[nt][3] * inv1)));
    }
}

// ---------------- launch ----------------
extern "C" void kernel_launch(void* const* d_in, const int* in_sizes, int n_in,
                              void* d_out, int out_size) {
    const float* x   = (const float*)d_in[0];
    const void*  ctx = d_in[1];
    const float* Wq  = (const float*)d_in[2];
    const float* bq  = (const float*)d_in[3];
    const float* Wk  = (const float*)d_in[4];
    const float* bk  = (const float*)d_in[5];
    const float* Wv  = (const float*)d_in[6];
    const float* bv  = (const float*)d_in[7];
    const float* Wo  = (const float*)d_in[8];
    const float* bo  = (const float*)d_in[9];
    float* out = (float*)d_out;

    __half *qh, *kh, *vh;
    float *ab, *xt, *wq, *wk, *wv, *wo;
    cudaGetSymbolAddress((void**)&qh, g_qh);
    cudaGetSymbolAddress((void**)&kh, g_kh);
    cudaGetSymbolAddress((void**)&vh, g_vh);
    cudaGetSymbolAddress((void**)&ab, g_att);
    cudaGetSymbolAddress((void**)&xt, g_xt);
    cudaGetSymbolAddress((void**)&wq, g_wq);
    cudaGetSymbolAddress((void**)&wk, g_wk);
    cudaGetSymbolAddress((void**)&wv, g_wv);
    cudaGetSymbolAddress((void**)&wo, g_wo);

    static bool attr_set = false;
    if (!attr_set) {
        cudaFuncSetAttribute(gemm_tc_kernel, cudaFuncAttributeMaxDynamicSharedMemorySize,
                             4 * GBUF * (int)sizeof(float));
        attr_set = true;
    }

    detect_dtype_kernel<<<1, 1024>>>((const unsigned char*)ctx, MTOT);
    ctx_convert_kernel<<<(MTOT + 255) / 256, 256>>>(ctx, MTOT);
    build_perm_kernel<<<BATCH, 256>>>();

    tf32_convert_all_kernel<<<1184, 256>>>(x, Wq, Wk, Wv, Wo);

    int smem = 4 * GBUF * (int)sizeof(float);   // 73728 B

    dim3 gqkv(DMODEL / 128, MTOT / 128, 3);
    gemm_tc_kernel<<<gqkv, 256, smem>>>(xt, wq, bq, qh, wk, bk, kh, wv, bv, vh, 1);

    attn_tc_kernel<<<dim3(SEQ / 128, NHEAD, BATCH), 256>>>();

    dim3 go(DMODEL / 128, MTOT / 128, 1);
    gemm_tc_kernel<<<go, 256, smem>>>(ab, wo, bo, out, wo, bo, out, wo, bo, out, 0);
}

// round 14
// speedup vs baseline: 2.3365x; 1.3153x over previous
#include <cuda_runtime.h>
#include <cuda_fp16.h>
#include <math.h>
#include <stdint.h>

#define BATCH  4
#define SEQ    2048
#define DMODEL 768
#define NHEAD  12
#define HDIM   64
#define MTOT   (BATCH*SEQ)

// ---------------- scratch (static device globals; no allocs allowed) ----------------
__device__ __half g_qh[MTOT*DMODEL];   // Q (x Wq^T + b) * 0.125, half, ctx-sorted rows
__device__ __half g_kh[MTOT*DMODEL];   // K, half, ctx-sorted rows
__device__ __half g_vh[MTOT*DMODEL];   // V^T, half: [b,h][dim][key(sorted)]
__device__ __half g_atth[MTOT*DMODEL]; // attention out, half, ORIGINAL rows (O GEMM input)
__device__ __half g_xh[MTOT*DMODEL];   // x, half
__device__ __half g_wqh[DMODEL*DMODEL];// weights, half
__device__ __half g_wkh[DMODEL*DMODEL];
__device__ __half g_wvh[DMODEL*DMODEL];
__device__ __half g_woh[DMODEL*DMODEL];
__device__ unsigned char g_ctx[MTOT];
__device__ int g_perm[MTOT];           // perm[new] = old  (per batch, ctx rows first)
__device__ int g_inv[MTOT];            // inv[old] = new
__device__ int g_nctx[BATCH];
__device__ int g_is_byte;

// ---------------- is_context dtype detection ----------------
__global__ void detect_dtype_kernel(const unsigned char* __restrict__ p, int nbytes) {
    __shared__ int found;
    if (threadIdx.x == 0) found = 0;
    __syncthreads();
    int loc = 0;
    for (int i = threadIdx.x; i < nbytes; i += blockDim.x)
        if ((i & 3) == 1 && p[i] != 0) loc = 1;
    if (loc) atomicOr(&found, 1);
    __syncthreads();
    if (threadIdx.x == 0) g_is_byte = found;
}

__global__ void ctx_convert_kernel(const void* __restrict__ p, int n) {
    int i = blockIdx.x * blockDim.x + threadIdx.x;
    if (i >= n) return;
    int v;
    if (g_is_byte) v = ((const unsigned char*)p)[i];
    else           v = ((const int*)p)[i];
    g_ctx[i] = v ? 1 : 0;
}

// ---------------- stable partition (ctx first) per batch: block scan ----------------
__global__ void build_perm_kernel() {
    __shared__ int partial[256];
    int b = blockIdx.x, t = threadIdx.x;
    int flags[8];
    int cnt = 0;
#pragma unroll
    for (int i = 0; i < 8; i++) {
        flags[i] = g_ctx[b * SEQ + t * 8 + i];
        cnt += flags[i];
    }
    partial[t] = cnt;
    __syncthreads();
    for (int off = 1; off < 256; off <<= 1) {
        int v = (t >= off) ? partial[t - off] : 0;
        __syncthreads();
        partial[t] += v;
        __syncthreads();
    }
    int total = partial[255];
    int run = partial[t] - cnt;
#pragma unroll
    for (int i = 0; i < 8; i++) {
        int old = t * 8 + i;
        int newpos;
        if (flags[i]) { newpos = run; run++; }
        else          { newpos = total + (old - run); }
        g_perm[b * SEQ + newpos] = old;
        g_inv[b * SEQ + old] = newpos;
    }
    if (t == 0) g_nctx[b] = total;
}

// ---------------- helpers ----------------
// fp16 mma, fp32 accumulate: D(16x8) = A(16x16,row) * B(16x8,col) + C
__device__ __forceinline__ void mma_f16(float* d, const uint32_t* a, const uint32_t* b, const float* c) {
    asm volatile(
        "mma.sync.aligned.m16n8k16.row.col.f32.f16.f16.f32 "
        "{%0,%1,%2,%3}, {%4,%5,%6,%7}, {%8,%9}, {%10,%11,%12,%13};"
        : "=f"(d[0]), "=f"(d[1]), "=f"(d[2]), "=f"(d[3])
        : "r"(a[0]), "r"(a[1]), "r"(a[2]), "r"(a[3]),
          "r"(b[0]), "r"(b[1]),
          "f"(c[0]), "f"(c[1]), "f"(c[2]), "f"(c[3]));
}

__device__ __forceinline__ uint32_t pack_h2(float lo, float hi) {
    __half2 h = __floats2half2_rn(lo, hi);
    return *(uint32_t*)&h;
}

__device__ __forceinline__ void cp_async16(uint32_t saddr, const void* gptr) {
    asm volatile("cp.async.cg.shared.global [%0], [%1], 16;" :: "r"(saddr), "l"(gptr));
}
__device__ __forceinline__ void cp_commit() {
    asm volatile("cp.async.commit_group;" ::: "memory");
}
__device__ __forceinline__ void cp_wait1() {
    asm volatile("cp.async.wait_group 1;" ::: "memory");
}
__device__ __forceinline__ void cp_wait0() {
    asm volatile("cp.async.wait_group 0;" ::: "memory");
}

// ---------------- fused half pre-conversion: x + all 4 weights in ONE launch ----------------
#define NX (MTOT*DMODEL)
#define NW (DMODEL*DMODEL)
__global__ void half_convert_all_kernel(const float* __restrict__ x,
                                        const float* __restrict__ Wq,
                                        const float* __restrict__ Wk,
                                        const float* __restrict__ Wv,
                                        const float* __restrict__ Wo) {
    int total = NX + 4 * NW;
    int stride = gridDim.x * blockDim.x;
    for (int i = blockIdx.x * blockDim.x + threadIdx.x; i < total; i += stride) {
        if (i < NX) {
            g_xh[i] = __float2half_rn(x[i]);
        } else {
            int j = i - NX;
            int wsel = j / NW;
            int off  = j - wsel * NW;
            const float* src = (wsel == 0) ? Wq : (wsel == 1) ? Wk : (wsel == 2) ? Wv : Wo;
            __half*      dst = (wsel == 0) ? g_wqh : (wsel == 1) ? g_wkh : (wsel == 2) ? g_wvh : g_woh;
            dst[off] = __float2half_rn(src[off]);
        }
    }
}

// ---------------- fp16 tensor-core GEMM, cp.async double-buffered, BK=64 ----------------
// C[M,768] = A[M,768] @ W[768,768]^T + bias, A/W half, accum fp32.
// out_mode=0: fp32 natural output (O projection).
// out_mode=1: fused QKV. z=0 -> Q half * 0.125, ctx-sorted rows; z=1 -> K half,
// ctx-sorted rows; z=2 -> V^T half, [b,h][dim][key(sorted)].
#define GROWH 72                 // halves per row (144 B; word stride 36 -> conflict-free)
#define GBUFH (128*GROWH)        // halves per buffer per array
__global__ __launch_bounds__(256, 2) void gemm_f16_kernel(
    const __half* __restrict__ A,
    const __half* __restrict__ W0, const float* __restrict__ b0, void* __restrict__ C0,
    const __half* __restrict__ W1, const float* __restrict__ b1, void* __restrict__ C1,
    const __half* __restrict__ W2, const float* __restrict__ b2, void* __restrict__ C2,
    int out_mode)
{
    extern __shared__ __half smh[];
    __half* As = smh;               // [2][128][GROWH]
    __half* Bs = smh + 2 * GBUFH;   // [2][128][GROWH]

    int z = blockIdx.z;
    const __half* W   = (z == 0) ? W0 : (z == 1) ? W1 : W2;
    const float* bias = (z == 0) ? b0 : (z == 1) ? b1 : b2;
    void*        C    = (z == 0) ? C0 : (z == 1) ? C1 : C2;

    int t    = threadIdx.x;
    int lane = t & 31;
    int warp = t >> 5;
    int g    = lane >> 2;
    int tq   = lane & 3;
    int wm   = (warp & 3) * 32;
    int wn   = (warp >> 2) * 64;
    int m0   = blockIdx.y * 128;
    int n0   = blockIdx.x * 128;

    float acc[2][8][4];
#pragma unroll
    for (int mt = 0; mt < 2; mt++)
#pragma unroll
        for (int nt = 0; nt < 8; nt++)
#pragma unroll
            for (int c = 0; c < 4; c++) acc[mt][nt][c] = 0.f;

    uint32_t as_s = (uint32_t)__cvta_generic_to_shared(As);
    uint32_t bs_s = (uint32_t)__cvta_generic_to_shared(Bs);

    // stage one BK=64 slab (128 rows x 64 halves = 128 B/row = 8 chunks/row)
    auto stage = [&](int buf, int k0) {
        uint32_t bo = (uint32_t)buf * GBUFH * 2;
#pragma unroll
        for (int u = 0; u < 4; u++) {
            int c = t + 256 * u;          // 1024 chunks per array
            int row = c >> 3, c16 = c & 7;
            uint32_t soff = bo + (uint32_t)(row * GROWH + c16 * 8) * 2;
            cp_async16(as_s + soff, A + (size_t)(m0 + row) * DMODEL + k0 + c16 * 8);
            cp_async16(bs_s + soff, W + (size_t)(n0 + row) * DMODEL + k0 + c16 * 8);
        }
        cp_commit();
    };

    stage(0, 0);

    const int NI = DMODEL / 64;   // 12
    for (int iter = 0; iter < NI; iter++) {
        int buf = iter & 1;
        if (iter + 1 < NI) {
            stage(buf ^ 1, (iter + 1) * 64);
            cp_wait1();
        } else {
            cp_wait0();
        }
        __syncthreads();

        const __half* A2 = As + buf * GBUFH;
        const __half* B2 = Bs + buf * GBUFH;

#pragma unroll
        for (int kst = 0; kst < 4; kst++) {    // 4 x k16
            int kb = kst * 16;
            uint32_t af[2][4];
#pragma unroll
            for (int mt = 0; mt < 2; mt++) {
                int rb = wm + mt * 16;
                af[mt][0] = *(const uint32_t*)&A2[(rb + g    ) * GROWH + kb + 2*tq    ];
                af[mt][1] = *(const uint32_t*)&A2[(rb + g + 8) * GROWH + kb + 2*tq    ];
                af[mt][2] = *(const uint32_t*)&A2[(rb + g    ) * GROWH + kb + 2*tq + 8];
                af[mt][3] = *(const uint32_t*)&A2[(rb + g + 8) * GROWH + kb + 2*tq + 8];
            }
#pragma unroll
            for (int nt = 0; nt < 8; nt++) {
                uint32_t bf[2];
                bf[0] = *(const uint32_t*)&B2[(wn + nt*8 + g) * GROWH + kb + 2*tq    ];
                bf[1] = *(const uint32_t*)&B2[(wn + nt*8 + g) * GROWH + kb + 2*tq + 8];
                mma_f16(acc[0][nt], af[0], bf, acc[0][nt]);
                mma_f16(acc[1][nt], af[1], bf, acc[1][nt]);
            }
        }
        __syncthreads();
    }

#pragma unroll
    for (int mt = 0; mt < 2; mt++) {
        int row = m0 + wm + mt * 16 + g;
        int r0 = row, r1 = row + 8;
        if (out_mode) {   // ctx-sorted scatter (rows stay within batch: SEQ-aligned tiles)
            r0 = (row & ~(SEQ - 1)) + g_inv[row];
            r1 = ((row + 8) & ~(SEQ - 1)) + g_inv[row + 8];
        }
#pragma unroll
        for (int nt = 0; nt < 8; nt++) {
            int col = n0 + wn + nt * 8 + 2 * tq;
            float b0v = bias[col], b1v = bias[col + 1];
            float v00 = acc[mt][nt][0] + b0v, v01 = acc[mt][nt][1] + b1v;
            float v10 = acc[mt][nt][2] + b0v, v11 = acc[mt][nt][3] + b1v;
            if (!out_mode) {
                float* Cf = (float*)C;
                *(float2*)&Cf[(size_t)r0 * DMODEL + col] = make_float2(v00, v01);
                *(float2*)&Cf[(size_t)r1 * DMODEL + col] = make_float2(v10, v11);
            } else if (z <= 1) {
                // Q (scaled) / K: half2, sorted rows, natural [row][dim]
                float s = (z == 0) ? 0.125f : 1.0f;
                __half* Ch = (__half*)C;
                *(uint32_t*)&Ch[(size_t)r0 * DMODEL + col] = pack_h2(v00 * s, v01 * s);
                *(uint32_t*)&Ch[(size_t)r1 * DMODEL + col] = pack_h2(v10 * s, v11 * s);
            } else {
                // V^T half: [b,h][dim][key]; key = sorted row within batch
                __half* Vh = (__half*)C;
                int hh = col >> 6, d = col & 63;
                int b0i = r0 >> 11, k0i = r0 & (SEQ - 1);
                int b1i = r1 >> 11, k1i = r1 & (SEQ - 1);
                size_t base0 = (((size_t)b0i * NHEAD + hh) * HDIM + d) * SEQ;
                size_t base1 = (((size_t)b1i * NHEAD + hh) * HDIM + d) * SEQ;
                Vh[base0 + k0i]       = __float2half_rn(v00);
                Vh[base0 + SEQ + k0i] = __float2half_rn(v01);   // d+1
                Vh[base1 + k1i]       = __float2half_rn(v10);
                Vh[base1 + SEQ + k1i] = __float2half_rn(v11);
            }
        }
    }
}

// ---------------- Flash attention: fp16 m16n8k16, ctx-sorted, cp.async 2-buf (round-13, kept) ----------------
__global__ __launch_bounds__(256, 2) void attn_tc_kernel() {
    __shared__ __align__(16) uint32_t Ksw[2][32][36];
    __shared__ __align__(16) uint32_t Vtw[2][64][20];
    __shared__ __align__(16) uint32_t Ps[8][16][20];

    int t    = threadIdx.x;
    int lane = t & 31;
    int w    = t >> 5;
    int g    = lane >> 2;
    int tq   = lane & 3;

    int b  = blockIdx.z;
    int h  = blockIdx.y;
    int qrow = blockIdx.x * 128 + w * 16;     // sorted position
    int nctx = g_nctx[b];

    bool all_ctx = (blockIdx.x * 128 + 128) <= nctx;
    int NT_cta = all_ctx ? (nctx + 31) / 32 : (SEQ / 32);

    uint32_t qa[4][4];
    {
        const __half* qb = g_qh + (size_t)(b * SEQ + qrow) * DMODEL + h * HDIM;
#pragma unroll
        for (int kst = 0; kst < 4; kst++) {
            qa[kst][0] = *(const uint32_t*)&qb[(size_t)g       * DMODEL + kst*16 + 2*tq    ];
            qa[kst][1] = *(const uint32_t*)&qb[(size_t)(g + 8) * DMODEL + kst*16 + 2*tq    ];
            qa[kst][2] = *(const uint32_t*)&qb[(size_t)g       * DMODEL + kst*16 + 2*tq + 8];
            qa[kst][3] = *(const uint32_t*)&qb[(size_t)(g + 8) * DMODEL + kst*16 + 2*tq + 8];
        }
    }
    float rf0 = (qrow + g     < nctx) ? 1.f : 0.f;
    float rf1 = (qrow + g + 8 < nctx) ? 1.f : 0.f;

    float o[8][4];
#pragma unroll
    for (int nt = 0; nt < 8; nt++)
#pragma unroll
        for (int c = 0; c < 4; c++) o[nt][c] = 0.f;
    float m0r = -1e30f, m1r = -1e30f, l0 = 0.f, l1 = 0.f;

    int kkey = t >> 3, kc = t & 7;
    int vdim = t >> 2, vc = t & 3;
    const __half* kb_g = g_kh + (size_t)(b * SEQ) * DMODEL + h * HDIM;
    const __half* vb_g = g_vh + ((size_t)b * NHEAD + h) * HDIM * SEQ;

    uint32_t ks_s = (uint32_t)__cvta_generic_to_shared(&Ksw[0][0][0]);
    uint32_t vs_s = (uint32_t)__cvta_generic_to_shared(&Vtw[0][0][0]);
    const uint32_t KBUF = 32 * 36 * 4;
    const uint32_t VBUF = 64 * 20 * 4;

    auto stage = [&](int buf, int kt) {
        cp_async16(ks_s + buf * KBUF + (uint32_t)(kkey * 36 + kc * 4) * 4,
                   kb_g + (size_t)(kt + kkey) * DMODEL + kc * 8);
        cp_async16(vs_s + buf * VBUF + (uint32_t)(vdim * 20 + vc * 4) * 4,
                   vb_g + (size_t)vdim * SEQ + kt + vc * 8);
        cp_commit();
    };

    stage(0, 0);

    for (int tile = 0; tile < NT_cta; tile++) {
        int buf = tile & 1;
        if (tile + 1 < NT_cta) {
            stage(buf ^ 1, (tile + 1) * 32);
            cp_wait1();
        } else {
            cp_wait0();
        }
        __syncthreads();

        int k0b = tile * 32;

        // ---- S = Q K^T (16 x 32) ----
        float sacc[4][4];
#pragma unroll
        for (int nt = 0; nt < 4; nt++)
#pragma unroll
            for (int c = 0; c < 4; c++) sacc[nt][c] = 0.f;
#pragma unroll
        for (int kst = 0; kst < 4; kst++) {
#pragma unroll
            for (int nt = 0; nt < 4; nt++) {
                uint32_t bf[2];
                bf[0] = Ksw[buf][nt*8 + g][kst*8 + tq    ];
                bf[1] = Ksw[buf][nt*8 + g][kst*8 + tq + 4];
                mma_f16(sacc[nt], qa[kst], bf, sacc[nt]);
            }
        }

        // ---- mask (additive -1e30; only when tile straddles/exceeds ctx region) ----
        if (k0b + 32 > nctx) {
#pragma unroll
            for (int nt = 0; nt < 4; nt++) {
                int col = k0b + nt*8 + 2*tq;
                float k0m = (col     < nctx) ? 0.f : -1e30f;
                float k1m = (col + 1 < nctx) ? 0.f : -1e30f;
                sacc[nt][0] = fmaf(rf0, k0m, sacc[nt][0]);
                sacc[nt][1] = fmaf(rf0, k1m, sacc[nt][1]);
                sacc[nt][2] = fmaf(rf1, k0m, sacc[nt][2]);
                sacc[nt][3] = fmaf(rf1, k1m, sacc[nt][3]);
            }
        }

        // ---- online softmax (MUFU exps) ----
        float mx0 = -1e30f, mx1 = -1e30f;
#pragma unroll
        for (int nt = 0; nt < 4; nt++) {
            mx0 = fmaxf(mx0, fmaxf(sacc[nt][0], sacc[nt][1]));
            mx1 = fmaxf(mx1, fmaxf(sacc[nt][2], sacc[nt][3]));
        }
        mx0 = fmaxf(mx0, __shfl_xor_sync(0xffffffffu, mx0, 1));
        mx0 = fmaxf(mx0, __shfl_xor_sync(0xffffffffu, mx0, 2));
        mx1 = fmaxf(mx1, __shfl_xor_sync(0xffffffffu, mx1, 1));
        mx1 = fmaxf(mx1, __shfl_xor_sync(0xffffffffu, mx1, 2));

        float mn0 = fmaxf(m0r, mx0), mn1 = fmaxf(m1r, mx1);
        float corr0 = __expf(m0r - mn0), corr1 = __expf(m1r - mn1);
        m0r = mn0; m1r = mn1;

        float rs0 = 0.f, rs1 = 0.f;
        __syncwarp();
#pragma unroll
        for (int nt = 0; nt < 4; nt++) {
            float p00 = __expf(sacc[nt][0] - mn0);
            float p01 = __expf(sacc[nt][1] - mn0);
            float p10 = __expf(sacc[nt][2] - mn1);
            float p11 = __expf(sacc[nt][3] - mn1);
            rs0 += p00 + p01; rs1 += p10 + p11;
            int pw = nt*4 + tq;
            Ps[w][g    ][pw] = pack_h2(p00, p01);
            Ps[w][g + 8][pw] = pack_h2(p10, p11);
        }
        rs0 += __shfl_xor_sync(0xffffffffu, rs0, 1);
        rs0 += __shfl_xor_sync(0xffffffffu, rs0, 2);
        rs1 += __shfl_xor_sync(0xffffffffu, rs1, 1);
        rs1 += __shfl_xor_sync(0xffffffffu, rs1, 2);
        l0 = l0 * corr0 + rs0;
        l1 = l1 * corr1 + rs1;

#pragma unroll
        for (int nt = 0; nt < 8; nt++) {
            o[nt][0] *= corr0; o[nt][1] *= corr0;
            o[nt][2] *= corr1; o[nt][3] *= corr1;
        }
        __syncwarp();

        // ---- O += P V (16 x 64, k=32) ----
#pragma unroll
        for (int c2 = 0; c2 < 2; c2++) {
            uint32_t ap[4];
            ap[0] = Ps[w][g    ][c2*8 + tq    ];
            ap[1] = Ps[w][g + 8][c2*8 + tq    ];
            ap[2] = Ps[w][g    ][c2*8 + tq + 4];
            ap[3] = Ps[w][g + 8][c2*8 + tq + 4];
#pragma unroll
            for (int nt = 0; nt < 8; nt++) {
                uint32_t bf[2];
                bf[0] = Vtw[buf][nt*8 + g][c2*8 + tq    ];
                bf[1] = Vtw[buf][nt*8 + g][c2*8 + tq + 4];
                mma_f16(o[nt], ap, bf, o[nt]);
            }
        }
        __syncthreads();
    }

    // ---- normalize + write back to ORIGINAL rows as HALF (O GEMM input) ----
    float inv0 = 1.f / l0, inv1 = 1.f / l1;
    int orow0 = g_perm[b * SEQ + qrow + g    ];
    int orow1 = g_perm[b * SEQ + qrow + g + 8];
    __half* ob0 = g_atth + ((size_t)b * SEQ + orow0) * DMODEL + h * HDIM;
    __half* ob1 = g_atth + ((size_t)b * SEQ + orow1) * DMODEL + h * HDIM;
#pragma unroll
    for (int nt = 0; nt < 8; nt++) {
        int col = nt*8 + 2*tq;
        *(uint32_t*)&ob0[col] = pack_h2(o[nt][0] * inv0, o[nt][1] * inv0);
        *(uint32_t*)&ob1[col] = pack_h2(o[nt][2] * inv1, o[nt][3] * inv1);
    }
}

// ---------------- launch ----------------
extern "C" void kernel_launch(void* const* d_in, const int* in_sizes, int n_in,
                              void* d_out, int out_size) {
    const float* x   = (const float*)d_in[0];
    const void*  ctx = d_in[1];
    const float* Wq  = (const float*)d_in[2];
    const float* bq  = (const float*)d_in[3];
    const float* Wk  = (const float*)d_in[4];
    const float* bk  = (const float*)d_in[5];
    const float* Wv  = (const float*)d_in[6];
    const float* bv  = (const float*)d_in[7];
    const float* Wo  = (const float*)d_in[8];
    const float* bo  = (const float*)d_in[9];
    float* out = (float*)d_out;

    __half *qh, *kh, *vh, *ath, *xh, *wqh, *wkh, *wvh, *woh;
    cudaGetSymbolAddress((void**)&qh,  g_qh);
    cudaGetSymbolAddress((void**)&kh,  g_kh);
    cudaGetSymbolAddress((void**)&vh,  g_vh);
    cudaGetSymbolAddress((void**)&ath, g_atth);
    cudaGetSymbolAddress((void**)&xh,  g_xh);
    cudaGetSymbolAddress((void**)&wqh, g_wqh);
    cudaGetSymbolAddress((void**)&wkh, g_wkh);
    cudaGetSymbolAddress((void**)&wvh, g_wvh);
    cudaGetSymbolAddress((void**)&woh, g_woh);

    static bool attr_set = false;
    if (!attr_set) {
        cudaFuncSetAttribute(gemm_f16_kernel, cudaFuncAttributeMaxDynamicSharedMemorySize,
                             4 * GBUFH * (int)sizeof(__half));
        attr_set = true;
    }

    detect_dtype_kernel<<<1, 1024>>>((const unsigned char*)ctx, MTOT);
    ctx_convert_kernel<<<(MTOT + 255) / 256, 256>>>(ctx, MTOT);
    build_perm_kernel<<<BATCH, 256>>>();

    half_convert_all_kernel<<<1184, 256>>>(x, Wq, Wk, Wv, Wo);

    int smem = 4 * GBUFH * (int)sizeof(__half);   // 73728 B

    dim3 gqkv(DMODEL / 128, MTOT / 128, 3);
    gemm_f16_kernel<<<gqkv, 256, smem>>>(xh, wqh, bq, qh, wkh, bk, kh, wvh, bv, vh, 1);

    attn_tc_kernel<<<dim3(SEQ / 128, NHEAD, BATCH), 256>>>();

    dim3 go(DMODEL / 128, MTOT / 128, 1);
    gemm_f16_kernel<<<go, 256, smem>>>(ath, woh, bo, out, woh, bo, out, woh, bo, out, 0);
}